// round 1
// baseline (speedup 1.0000x reference)
#include <cuda_runtime.h>
#include <math.h>
#include <stdint.h>

// ---------------------------------------------------------------------------
// WindowCrossAttention  B=4096, N=64, C=256, H=8, Dh=32
//   qkv1 = x @ Wqkv1 + bqkv1            (262144 x 768)
//   qkv2 = y @ Wqkv2 + bqkv2
//   attn1 = softmax(q1 k2^T / 16 + bias1) v2 -> o1 (B,N,C)
//   attn2 = softmax(q2 k1^T / 16 + bias2) v1 -> o2
//   out1 = LN(o1 @ Wp1 + bp1 + x; g1,be1)
//   out2 = LN(o2 @ Wp2 + bp2 + y; g2,be2)
// ---------------------------------------------------------------------------

#define Bwin 4096
#define Ntok 64
#define Cch  256
#define Hh   8
#define Dh   32
#define Mrows (Bwin * Ntok)            // 262144

// scratch (static device arrays; no allocations allowed)
__device__ float g_qkv1[(size_t)Mrows * 768];
__device__ float g_qkv2[(size_t)Mrows * 768];
__device__ float g_o1[(size_t)Mrows * Cch];
__device__ float g_o2[(size_t)Mrows * Cch];
__device__ float g_p1[(size_t)Mrows * Cch];
__device__ float g_p2[(size_t)Mrows * Cch];

// ---------------------------------------------------------------------------
// SGEMM: C = A(M x 256) @ W(256 x Nc) + bias(Nc)
// BM=128, BN=64, BK=16, 256 threads, TM=8, TN=4
// ---------------------------------------------------------------------------
#define BM 128
#define BN 64
#define BK 16
#define TM 8
#define TN 4

__global__ __launch_bounds__(256, 2)
void sgemm_bias(const float* __restrict__ A, const float* __restrict__ W,
                const float* __restrict__ bias, float* __restrict__ C,
                int Nc) {
    const int K = 256;
    __shared__ float As[BK][BM];     // transposed: As[k][m]
    __shared__ float Bs[BK][BN];

    const int tid = threadIdx.x;
    const int tx = tid & 15;         // n-group 0..15
    const int ty = tid >> 4;         // m-group 0..15
    const int mBase = blockIdx.y * BM;
    const int nBase = blockIdx.x * BN;

    float acc[TM][TN];
#pragma unroll
    for (int i = 0; i < TM; i++)
#pragma unroll
        for (int j = 0; j < TN; j++) acc[i][j] = 0.0f;

    for (int kc = 0; kc < K; kc += BK) {
        // load A tile: 128 x 16 floats = 512 float4, 2 per thread
#pragma unroll
        for (int r = 0; r < 2; r++) {
            int i = tid + 256 * r;
            int row = i >> 2;            // 0..127
            int c4 = i & 3;              // 0..3
            float4 v = *(const float4*)(A + (size_t)(mBase + row) * K + kc + c4 * 4);
            As[c4 * 4 + 0][row] = v.x;
            As[c4 * 4 + 1][row] = v.y;
            As[c4 * 4 + 2][row] = v.z;
            As[c4 * 4 + 3][row] = v.w;
        }
        // load B tile: 16 x 64 floats = 256 float4, 1 per thread
        {
            int row = tid >> 4;          // 0..15
            int c4 = tid & 15;           // 0..15
            float4 v = *(const float4*)(W + (size_t)(kc + row) * Nc + nBase + c4 * 4);
            *(float4*)(&Bs[row][c4 * 4]) = v;
        }
        __syncthreads();

#pragma unroll
        for (int k = 0; k < BK; k++) {
            float a[TM];
#pragma unroll
            for (int i = 0; i < TM; i++) a[i] = As[k][ty * TM + i];
            float4 bv = *(const float4*)(&Bs[k][tx * TN]);
            float bb[TN] = {bv.x, bv.y, bv.z, bv.w};
#pragma unroll
            for (int i = 0; i < TM; i++)
#pragma unroll
                for (int j = 0; j < TN; j++) acc[i][j] += a[i] * bb[j];
        }
        __syncthreads();
    }

    // epilogue: add bias, vector store
    float4 bvec = *(const float4*)(bias + nBase + tx * TN);
#pragma unroll
    for (int i = 0; i < TM; i++) {
        float4 o;
        o.x = acc[i][0] + bvec.x;
        o.y = acc[i][1] + bvec.y;
        o.z = acc[i][2] + bvec.z;
        o.w = acc[i][3] + bvec.w;
        *(float4*)(C + (size_t)(mBase + ty * TM + i) * Nc + nBase + tx * TN) = o;
    }
}

// ---------------------------------------------------------------------------
// Attention: one block per (window b, head h); 64 threads, one row each.
//   out[(b*64+n)*256 + h*32+d] = softmax_m(q[n]·k[m]/16 + bias[h,n,m]) · v[m]
//   q from qkvQ cols [h*32, h*32+32); k from qkvKV cols [256+h*32, ...);
//   v from qkvKV cols [512+h*32, ...)
// ---------------------------------------------------------------------------
__global__ __launch_bounds__(64)
void attn_kernel(const float* __restrict__ qkvQ, const float* __restrict__ qkvKV,
                 const float* __restrict__ bias, float* __restrict__ out) {
    const int b = blockIdx.x;
    const int h = blockIdx.y;
    const int n = threadIdx.x;          // 0..63
    const float scale = 0.0625f;        // 1/sqrt(256)

    __shared__ float ks[64][33];
    __shared__ float vs[64][33];
    __shared__ float S[64][65];

    // cooperative load of K and V tiles (64 x 32 each)
#pragma unroll 4
    for (int r = 0; r < 32; r++) {
        int e = r * 64 + n;
        int m = e >> 5;
        int d = e & 31;
        size_t base = ((size_t)(b * 64 + m)) * 768 + h * 32 + d;
        ks[m][d] = qkvKV[base + 256];
        vs[m][d] = qkvKV[base + 512];
    }
    __syncthreads();

    float q[32];
    const float* qrow = qkvQ + ((size_t)(b * 64 + n)) * 768 + h * 32;
#pragma unroll
    for (int d = 0; d < 32; d++) q[d] = qrow[d];

    const float* brow = bias + ((size_t)h * 64 + n) * 64;

    float mx = -INFINITY;
#pragma unroll 2
    for (int m = 0; m < 64; m++) {
        float s = 0.0f;
#pragma unroll
        for (int d = 0; d < 32; d++) s += q[d] * ks[m][d];
        s = s * scale + brow[m];
        S[n][m] = s;
        mx = fmaxf(mx, s);
    }

    float sum = 0.0f;
#pragma unroll 4
    for (int m = 0; m < 64; m++) {
        float p = __expf(S[n][m] - mx);
        S[n][m] = p;
        sum += p;
    }
    float inv = 1.0f / sum;

    float o[32];
#pragma unroll
    for (int d = 0; d < 32; d++) o[d] = 0.0f;
#pragma unroll 2
    for (int m = 0; m < 64; m++) {
        float p = S[n][m];
#pragma unroll
        for (int d = 0; d < 32; d++) o[d] += p * vs[m][d];
    }

    float* orow = out + ((size_t)(b * 64 + n)) * 256 + h * 32;
#pragma unroll
    for (int d = 0; d < 32; d++) orow[d] = o[d] * inv;
}

// ---------------------------------------------------------------------------
// Residual + LayerNorm: one warp per row of 256
// ---------------------------------------------------------------------------
__global__ __launch_bounds__(256)
void ln_kernel(const float* __restrict__ p, const float* __restrict__ resid,
               const float* __restrict__ g, const float* __restrict__ be,
               float* __restrict__ out) {
    int row = (blockIdx.x * blockDim.x + threadIdx.x) >> 5;
    int lane = threadIdx.x & 31;
    if (row >= Mrows) return;

    const float* pr = p + (size_t)row * 256;
    const float* rr = resid + (size_t)row * 256;

    float v[8];
    float s = 0.0f, sq = 0.0f;
#pragma unroll
    for (int j = 0; j < 8; j++) {
        float t = pr[lane + 32 * j] + rr[lane + 32 * j];
        v[j] = t;
        s += t;
        sq += t * t;
    }
#pragma unroll
    for (int o = 16; o; o >>= 1) {
        s += __shfl_xor_sync(0xffffffffu, s, o);
        sq += __shfl_xor_sync(0xffffffffu, sq, o);
    }
    float mean = s * (1.0f / 256.0f);
    float var = sq * (1.0f / 256.0f) - mean * mean;
    float r = rsqrtf(var + 1e-5f);

    float* orow = out + (size_t)row * 256;
#pragma unroll
    for (int j = 0; j < 8; j++) {
        int d = lane + 32 * j;
        orow[d] = (v[j] - mean) * r * g[d] + be[d];
    }
}

// ---------------------------------------------------------------------------
// launch
// ---------------------------------------------------------------------------
extern "C" void kernel_launch(void* const* d_in, const int* in_sizes, int n_in,
                              void* d_out, int out_size) {
    const float* x     = (const float*)d_in[0];
    const float* y     = (const float*)d_in[1];
    const float* Wqkv1 = (const float*)d_in[2];
    const float* bqkv1 = (const float*)d_in[3];
    const float* Wqkv2 = (const float*)d_in[4];
    const float* bqkv2 = (const float*)d_in[5];
    const float* bias1 = (const float*)d_in[6];
    const float* bias2 = (const float*)d_in[7];
    const float* Wp1   = (const float*)d_in[8];
    const float* bp1   = (const float*)d_in[9];
    const float* Wp2   = (const float*)d_in[10];
    const float* bp2   = (const float*)d_in[11];
    const float* g1    = (const float*)d_in[12];
    const float* be1   = (const float*)d_in[13];
    const float* g2    = (const float*)d_in[14];
    const float* be2   = (const float*)d_in[15];
    float* out = (float*)d_out;

    float *qkv1, *qkv2, *o1, *o2, *p1, *p2;
    cudaGetSymbolAddress((void**)&qkv1, g_qkv1);
    cudaGetSymbolAddress((void**)&qkv2, g_qkv2);
    cudaGetSymbolAddress((void**)&o1, g_o1);
    cudaGetSymbolAddress((void**)&o2, g_o2);
    cudaGetSymbolAddress((void**)&p1, g_p1);
    cudaGetSymbolAddress((void**)&p2, g_p2);

    // phase 1: QKV projections (M=262144, K=256, N=768)
    dim3 gQKV(768 / BN, Mrows / BM);
    sgemm_bias<<<gQKV, 256>>>(x, Wqkv1, bqkv1, qkv1, 768);
    sgemm_bias<<<gQKV, 256>>>(y, Wqkv2, bqkv2, qkv2, 768);

    // phase 2: cross attention, both directions
    dim3 gA(Bwin, Hh);
    attn_kernel<<<gA, 64>>>(qkv1, qkv2, bias1, o1);  // q1 vs k2,v2
    attn_kernel<<<gA, 64>>>(qkv2, qkv1, bias2, o2);  // q2 vs k1,v1

    // phase 3: output projections (M=262144, K=256, N=256)
    dim3 gP(Cch / BN, Mrows / BM);
    sgemm_bias<<<gP, 256>>>(o1, Wp1, bp1, p1, Cch);
    sgemm_bias<<<gP, 256>>>(o2, Wp2, bp2, p2, Cch);

    // phase 4: residual + layernorm
    int lnBlocks = Mrows / 8;   // 8 warps (rows) per block
    ln_kernel<<<lnBlocks, 256>>>(p1, x, g1, be1, out);
    ln_kernel<<<lnBlocks, 256>>>(p2, y, g2, be2, out + (size_t)Mrows * Cch);
}

// round 3
// speedup vs baseline: 2.0471x; 2.0471x over previous
#include <cuda_runtime.h>
#include <math.h>
#include <stdint.h>

// ---------------------------------------------------------------------------
// WindowCrossAttention  B=4096, N=64, C=256, H=8, Dh=32
// Round 3: GEMMs via mma.sync tf32 (HMMA tensor pipe; tcgen05 PTX is rejected
// because the bench pipeline emits compute_103 PTX, not compute_103a).
// Fused 1-pass attention with transposed bias (coalesced L1 reads).
// ---------------------------------------------------------------------------

#define Bwin 4096
#define Ntok 64
#define Cch  256
#define Hh   8
#define Mrows (Bwin * Ntok)            // 262144

// scratch (static device arrays; no allocations allowed)
__device__ float g_qkv1[(size_t)Mrows * 768];
__device__ float g_qkv2[(size_t)Mrows * 768];
__device__ float g_o1[(size_t)Mrows * Cch];
__device__ float g_o2[(size_t)Mrows * Cch];
__device__ float g_p1[(size_t)Mrows * Cch];
__device__ float g_p2[(size_t)Mrows * Cch];
__device__ float g_wtq1[768 * 256];
__device__ float g_wtq2[768 * 256];
__device__ float g_wtp1[256 * 256];
__device__ float g_wtp2[256 * 256];
__device__ float g_bt1[Hh * 64 * 64];
__device__ float g_bt2[Hh * 64 * 64];

__device__ __forceinline__ uint32_t f2tf(float f) {
    uint32_t r;
    asm("cvt.rna.tf32.f32 %0, %1;" : "=r"(r) : "f"(f));
    return r;
}

// m16n8k8 tf32 HMMA. Memory fragment order is {a0,a2,a1,a3} relative to the
// PTX register order, hence the .z/.y swap.
__device__ __forceinline__ void mma8(float* c, uint4 a, uint2 b) {
    asm volatile(
        "mma.sync.aligned.m16n8k8.row.col.f32.tf32.tf32.f32 "
        "{%0,%1,%2,%3}, {%4,%5,%6,%7}, {%8,%9}, {%0,%1,%2,%3};"
        : "+f"(c[0]), "+f"(c[1]), "+f"(c[2]), "+f"(c[3])
        : "r"(a.x), "r"(a.z), "r"(a.y), "r"(a.w), "r"(b.x), "r"(b.y));
}

// ---------------------------------------------------------------------------
// Weight transpose + tf32 round: W (256 x Nc) -> Wt (Nc x 256)
// ---------------------------------------------------------------------------
__global__ void transpose_tf32(const float* __restrict__ W, float* __restrict__ Wt, int Nc) {
    __shared__ float tile[32][33];
    int n0 = blockIdx.x * 32;
    int k0 = blockIdx.y * 32;
    int tx = threadIdx.x, ty = threadIdx.y;   // (32, 8)
#pragma unroll
    for (int r = 0; r < 4; r++)
        tile[ty + 8 * r][tx] = W[(size_t)(k0 + ty + 8 * r) * Nc + n0 + tx];
    __syncthreads();
#pragma unroll
    for (int r = 0; r < 4; r++)
        Wt[(size_t)(n0 + ty + 8 * r) * 256 + k0 + tx] =
            __uint_as_float(f2tf(tile[tx][ty + 8 * r]));
}

// bias (H,64,64) [h][n][m] -> biasT [h][m][n]
__global__ void transpose_bias(const float* __restrict__ b, float* __restrict__ bt) {
    int h = blockIdx.x;
    const float* src = b + h * 4096;
    float* dst = bt + h * 4096;
    for (int i = threadIdx.x; i < 4096; i += 256)
        dst[i] = src[(i & 63) * 64 + (i >> 6)];
}

// ---------------------------------------------------------------------------
// tf32 HMMA GEMM: C(M x Nc) = A(M x 256) @ Wt^T + bias ; CTA tile 128x128
//   8 warps (2 m x 4 n), warp tile 64x32, BK=32, K=256 (8 chunks)
// Smem holds tiles in fragment-packed layout:
//   A: [kf(4)][mb(8)][lane(32)][4 x u32]  -> one LDS.128 per A fragment
//   B: [kf(4)][nb(16)][lane(32)][2 x u32] -> one LDS.64  per B fragment
// ---------------------------------------------------------------------------
__global__ __launch_bounds__(256, 2)
void gemm_tc(const float* __restrict__ A, const float* __restrict__ Bt,
             const float* __restrict__ bias, float* __restrict__ C, int Nc) {
    __shared__ uint32_t As[4096];
    __shared__ uint32_t Bs[4096];

    const int t = threadIdx.x;
    const int w = t >> 5;
    const int lane = t & 31;
    const int warp_m = w >> 2;           // 0..1
    const int warp_n = w & 3;            // 0..3
    const int mBase = blockIdx.y * 128;
    const int nBase = blockIdx.x * 128;

    const float* Ab = A + (size_t)mBase * 256;
    const float* Bb = Bt + (size_t)nBase * 256;

    float acc[4][4][4] = {};

    // loader indices (4 float4 per thread per tile): i = t + 256*r
    float4 sa[4], sb[4];
#pragma unroll
    for (int r = 0; r < 4; r++) {
        int i = t + 256 * r;
        int row = i >> 3, k4 = i & 7;
        sa[r] = *(const float4*)(Ab + (size_t)row * 256 + k4 * 4);
        sb[r] = *(const float4*)(Bb + (size_t)row * 256 + k4 * 4);
    }

#pragma unroll 1
    for (int c = 0; c < 8; c++) {
        // store staged chunk into packed-fragment smem (tf32 rounding here)
#pragma unroll
        for (int r = 0; r < 4; r++) {
            int i = t + 256 * r;
            int row = i >> 3, k4 = i & 7;
            int kf = k4 >> 1, klo = k4 & 1;
            int mb = row >> 4, mr = row & 15;
            uint32_t aoff = (uint32_t)(((kf * 8 + mb) * 32 + (mr & 7) * 4) * 4
                                       + klo + 2 * (mr >> 3));
            As[aoff + 0]  = f2tf(sa[r].x);
            As[aoff + 4]  = f2tf(sa[r].y);
            As[aoff + 8]  = f2tf(sa[r].z);
            As[aoff + 12] = f2tf(sa[r].w);
            int nb = row >> 3, nr = row & 7;
            uint32_t boff = (uint32_t)(((kf * 16 + nb) * 32 + nr * 4) * 2 + klo);
            Bs[boff + 0] = f2tf(sb[r].x);
            Bs[boff + 2] = f2tf(sb[r].y);
            Bs[boff + 4] = f2tf(sb[r].z);
            Bs[boff + 6] = f2tf(sb[r].w);
        }
        __syncthreads();

        // prefetch next chunk while computing
        if (c < 7) {
            int kc = (c + 1) * 32;
#pragma unroll
            for (int r = 0; r < 4; r++) {
                int i = t + 256 * r;
                int row = i >> 3, k4 = i & 7;
                sa[r] = *(const float4*)(Ab + (size_t)row * 256 + kc + k4 * 4);
                sb[r] = *(const float4*)(Bb + (size_t)row * 256 + kc + k4 * 4);
            }
        }

#pragma unroll
        for (int kf = 0; kf < 4; kf++) {
            uint4 av[4];
            uint2 bv[4];
#pragma unroll
            for (int mf = 0; mf < 4; mf++)
                av[mf] = *(const uint4*)&As[((kf * 8 + warp_m * 4 + mf) * 32 + lane) * 4];
#pragma unroll
            for (int nf = 0; nf < 4; nf++)
                bv[nf] = *(const uint2*)&Bs[((kf * 16 + warp_n * 4 + nf) * 32 + lane) * 2];
#pragma unroll
            for (int mf = 0; mf < 4; mf++)
#pragma unroll
                for (int nf = 0; nf < 4; nf++)
                    mma8(acc[mf][nf], av[mf], bv[nf]);
        }
        __syncthreads();
    }

    // epilogue: registers -> global, add bias
    const int g = lane >> 2;
    const int tq = lane & 3;
    float2 bz[4];
#pragma unroll
    for (int nf = 0; nf < 4; nf++)
        bz[nf] = *(const float2*)(bias + nBase + warp_n * 32 + nf * 8 + 2 * tq);

#pragma unroll
    for (int mf = 0; mf < 4; mf++) {
        int row0 = mBase + warp_m * 64 + mf * 16 + g;
#pragma unroll
        for (int nf = 0; nf < 4; nf++) {
            int col = nBase + warp_n * 32 + nf * 8 + 2 * tq;
            float2 o0 = { acc[mf][nf][0] + bz[nf].x, acc[mf][nf][1] + bz[nf].y };
            float2 o1 = { acc[mf][nf][2] + bz[nf].x, acc[mf][nf][3] + bz[nf].y };
            *(float2*)(C + (size_t)row0 * Nc + col) = o0;
            *(float2*)(C + (size_t)(row0 + 8) * Nc + col) = o1;
        }
    }
}

// ---------------------------------------------------------------------------
// Attention: one block per (window b, head h); 64 threads, one row each.
// Single pass: p = exp(q.k/16 + bias) (scores bounded; identical to softmax).
// biasT is [h][m][n] so inner-loop bias reads are coalesced.
// ---------------------------------------------------------------------------
__global__ __launch_bounds__(64)
void attn_kernel(const float* __restrict__ qkvQ, const float* __restrict__ qkvKV,
                 const float* __restrict__ biasT, float* __restrict__ out) {
    const int b = blockIdx.x;
    const int h = blockIdx.y;
    const int n = threadIdx.x;
    const float scale = 0.0625f;

    __shared__ float ks[64][36];
    __shared__ float vs[64][36];

    // cooperative vectorized load of K and V tiles (64 x 32 each)
#pragma unroll
    for (int r = 0; r < 8; r++) {
        int i = r * 64 + n;          // float4 index, 0..511
        int m = i >> 3;
        int d4 = i & 7;
        size_t base = ((size_t)(b * 64 + m)) * 768 + h * 32 + d4 * 4;
        *(float4*)&ks[m][d4 * 4] = *(const float4*)(qkvKV + base + 256);
        *(float4*)&vs[m][d4 * 4] = *(const float4*)(qkvKV + base + 512);
    }
    __syncthreads();

    float q[32];
    const float* qrow = qkvQ + ((size_t)(b * 64 + n)) * 768 + h * 32;
#pragma unroll
    for (int d4 = 0; d4 < 8; d4++)
        *(float4*)&q[d4 * 4] = *(const float4*)(qrow + d4 * 4);

    const float* bT = biasT + (size_t)h * 4096;

    float o[32];
#pragma unroll
    for (int d = 0; d < 32; d++) o[d] = 0.0f;
    float sum = 0.0f;

#pragma unroll 2
    for (int m = 0; m < 64; m++) {
        float s = 0.0f;
#pragma unroll
        for (int d = 0; d < 32; d++) s += q[d] * ks[m][d];
        float p = __expf(s * scale + bT[m * 64 + n]);
        sum += p;
#pragma unroll
        for (int d = 0; d < 32; d++) o[d] += p * vs[m][d];
    }
    float inv = 1.0f / sum;

    float* orow = out + ((size_t)(b * 64 + n)) * 256 + h * 32;
#pragma unroll
    for (int d4 = 0; d4 < 8; d4++) {
        float4 ov = { o[d4 * 4] * inv, o[d4 * 4 + 1] * inv,
                      o[d4 * 4 + 2] * inv, o[d4 * 4 + 3] * inv };
        *(float4*)(orow + d4 * 4) = ov;
    }
}

// ---------------------------------------------------------------------------
// Residual + LayerNorm: one warp per row of 256
// ---------------------------------------------------------------------------
__global__ __launch_bounds__(256)
void ln_kernel(const float* __restrict__ p, const float* __restrict__ resid,
               const float* __restrict__ g, const float* __restrict__ be,
               float* __restrict__ out) {
    int row = (blockIdx.x * blockDim.x + threadIdx.x) >> 5;
    int lane = threadIdx.x & 31;
    if (row >= Mrows) return;

    const float* pr = p + (size_t)row * 256;
    const float* rr = resid + (size_t)row * 256;

    float v[8];
    float s = 0.0f, sq = 0.0f;
#pragma unroll
    for (int j = 0; j < 8; j++) {
        float t = pr[lane + 32 * j] + rr[lane + 32 * j];
        v[j] = t;
        s += t;
        sq += t * t;
    }
#pragma unroll
    for (int o = 16; o; o >>= 1) {
        s += __shfl_xor_sync(0xffffffffu, s, o);
        sq += __shfl_xor_sync(0xffffffffu, sq, o);
    }
    float mean = s * (1.0f / 256.0f);
    float var = sq * (1.0f / 256.0f) - mean * mean;
    float r = rsqrtf(var + 1e-5f);

    float* orow = out + (size_t)row * 256;
#pragma unroll
    for (int j = 0; j < 8; j++) {
        int d = lane + 32 * j;
        orow[d] = (v[j] - mean) * r * g[d] + be[d];
    }
}

// ---------------------------------------------------------------------------
// launch
// ---------------------------------------------------------------------------
extern "C" void kernel_launch(void* const* d_in, const int* in_sizes, int n_in,
                              void* d_out, int out_size) {
    const float* x     = (const float*)d_in[0];
    const float* y     = (const float*)d_in[1];
    const float* Wqkv1 = (const float*)d_in[2];
    const float* bqkv1 = (const float*)d_in[3];
    const float* Wqkv2 = (const float*)d_in[4];
    const float* bqkv2 = (const float*)d_in[5];
    const float* bias1 = (const float*)d_in[6];
    const float* bias2 = (const float*)d_in[7];
    const float* Wp1   = (const float*)d_in[8];
    const float* bp1   = (const float*)d_in[9];
    const float* Wp2   = (const float*)d_in[10];
    const float* bp2   = (const float*)d_in[11];
    const float* g1    = (const float*)d_in[12];
    const float* be1   = (const float*)d_in[13];
    const float* g2    = (const float*)d_in[14];
    const float* be2   = (const float*)d_in[15];
    float* out = (float*)d_out;

    float *qkv1, *qkv2, *o1, *o2, *p1, *p2, *wtq1, *wtq2, *wtp1, *wtp2, *bt1, *bt2;
    cudaGetSymbolAddress((void**)&qkv1, g_qkv1);
    cudaGetSymbolAddress((void**)&qkv2, g_qkv2);
    cudaGetSymbolAddress((void**)&o1, g_o1);
    cudaGetSymbolAddress((void**)&o2, g_o2);
    cudaGetSymbolAddress((void**)&p1, g_p1);
    cudaGetSymbolAddress((void**)&p2, g_p2);
    cudaGetSymbolAddress((void**)&wtq1, g_wtq1);
    cudaGetSymbolAddress((void**)&wtq2, g_wtq2);
    cudaGetSymbolAddress((void**)&wtp1, g_wtp1);
    cudaGetSymbolAddress((void**)&wtp2, g_wtp2);
    cudaGetSymbolAddress((void**)&bt1, g_bt1);
    cudaGetSymbolAddress((void**)&bt2, g_bt2);

    // phase 0: transpose + tf32-round weights; transpose bias
    transpose_tf32<<<dim3(24, 8), dim3(32, 8)>>>(Wqkv1, wtq1, 768);
    transpose_tf32<<<dim3(24, 8), dim3(32, 8)>>>(Wqkv2, wtq2, 768);
    transpose_tf32<<<dim3(8, 8),  dim3(32, 8)>>>(Wp1,   wtp1, 256);
    transpose_tf32<<<dim3(8, 8),  dim3(32, 8)>>>(Wp2,   wtp2, 256);
    transpose_bias<<<Hh, 256>>>(bias1, bt1);
    transpose_bias<<<Hh, 256>>>(bias2, bt2);

    // phase 1: QKV projections (tensor pipe)
    dim3 gQKV(768 / 128, Mrows / 128);
    gemm_tc<<<gQKV, 256>>>(x, wtq1, bqkv1, qkv1, 768);
    gemm_tc<<<gQKV, 256>>>(y, wtq2, bqkv2, qkv2, 768);

    // phase 2: cross attention
    dim3 gA(Bwin, Hh);
    attn_kernel<<<gA, 64>>>(qkv1, qkv2, bt1, o1);
    attn_kernel<<<gA, 64>>>(qkv2, qkv1, bt2, o2);

    // phase 3: output projections (tensor pipe)
    dim3 gP(Cch / 128, Mrows / 128);
    gemm_tc<<<gP, 256>>>(o1, wtp1, bp1, p1, Cch);
    gemm_tc<<<gP, 256>>>(o2, wtp2, bp2, p2, Cch);

    // phase 4: residual + layernorm
    int lnBlocks = Mrows / 8;
    ln_kernel<<<lnBlocks, 256>>>(p1, x, g1, be1, out);
    ln_kernel<<<lnBlocks, 256>>>(p2, y, g2, be2, out + (size_t)Mrows * Cch);
}

// round 4
// speedup vs baseline: 4.2412x; 2.0718x over previous
#include <cuda_runtime.h>
#include <cuda_bf16.h>
#include <math.h>
#include <stdint.h>

// ---------------------------------------------------------------------------
// WindowCrossAttention  B=4096, N=64, C=256, H=8, Dh=32
// Round 4: bf16 m16n8k16 HMMA for GEMMs AND attention (QK^T + PV on tensor
// pipe, P repacked accumulator->A-fragment in registers). bf16 intermediates.
// ---------------------------------------------------------------------------

#define Bwin 4096
#define Hh   8
#define Mrows (Bwin * 64)              // 262144

typedef __nv_bfloat16 bf16;

// scratch (static device arrays; no allocations allowed)
__device__ bf16  g_qkv1[(size_t)Mrows * 768];
__device__ bf16  g_qkv2[(size_t)Mrows * 768];
__device__ bf16  g_o1[(size_t)Mrows * 256];
__device__ bf16  g_o2[(size_t)Mrows * 256];
__device__ float g_p1[(size_t)Mrows * 256];
__device__ float g_p2[(size_t)Mrows * 256];
__device__ bf16  g_wtq1[768 * 256];
__device__ bf16  g_wtq2[768 * 256];
__device__ bf16  g_wtp1[256 * 256];
__device__ bf16  g_wtp2[256 * 256];

__device__ __forceinline__ uint32_t pk(float lo, float hi) {
    __nv_bfloat162 t = __float22bfloat162_rn(make_float2(lo, hi));
    return *reinterpret_cast<uint32_t*>(&t);
}
__device__ __forceinline__ uint32_t smem_u32(const void* p) {
    uint32_t a;
    asm("{ .reg .u64 t; cvta.to.shared.u64 t, %1; cvt.u32.u64 %0, t; }"
        : "=r"(a) : "l"(p));
    return a;
}

// m16n8k16 bf16 HMMA; a0..a3 / b0,b1 in canonical PTX order.
__device__ __forceinline__ void mma16(float* c, uint4 a, uint2 b) {
    asm volatile(
        "mma.sync.aligned.m16n8k16.row.col.f32.bf16.bf16.f32 "
        "{%0,%1,%2,%3}, {%4,%5,%6,%7}, {%8,%9}, {%0,%1,%2,%3};"
        : "+f"(c[0]), "+f"(c[1]), "+f"(c[2]), "+f"(c[3])
        : "r"(a.x), "r"(a.y), "r"(a.z), "r"(a.w), "r"(b.x), "r"(b.y));
}

__device__ __forceinline__ uint2 ldsm_x2_trans(uint32_t addr) {
    uint2 r;
    asm volatile("ldmatrix.sync.aligned.m8n8.x2.trans.shared.b16 {%0,%1}, [%2];"
                 : "=r"(r.x), "=r"(r.y) : "r"(addr));
    return r;
}

// ---------------------------------------------------------------------------
// Weight transpose + bf16 round: W (256 x Nc) fp32 -> Wt (Nc x 256) bf16
// ---------------------------------------------------------------------------
__global__ void transpose_bf16(const float* __restrict__ W, bf16* __restrict__ Wt, int Nc) {
    __shared__ float tile[32][33];
    int n0 = blockIdx.x * 32;
    int k0 = blockIdx.y * 32;
    int tx = threadIdx.x, ty = threadIdx.y;   // (32, 8)
#pragma unroll
    for (int r = 0; r < 4; r++)
        tile[ty + 8 * r][tx] = W[(size_t)(k0 + ty + 8 * r) * Nc + n0 + tx];
    __syncthreads();
#pragma unroll
    for (int r = 0; r < 4; r++)
        Wt[(size_t)(n0 + ty + 8 * r) * 256 + k0 + tx] =
            __float2bfloat16_rn(tile[tx][ty + 8 * r]);
}

// ---------------------------------------------------------------------------
// bf16 HMMA GEMM: C(M x Nc) = A(M x 256) @ Wt^T + bias ; CTA tile 128x128
//   8 warps (2m x 4n), warp tile 64x32, BK=32, K=256 (8 chunks)
// Smem holds fragment-packed bf16x2 words:
//   A: [kf(2)][mb(8)][lane(32)][a0,a1,a2,a3]  -> LDS.128 per A fragment
//   B: [kf(2)][nb(16)][lane(32)][b0,b1]       -> LDS.64  per B fragment
// ---------------------------------------------------------------------------
template <class TIn, class TOut>
__global__ __launch_bounds__(256, 2)
void gemm_bf16(const TIn* __restrict__ A, const bf16* __restrict__ Bt,
               const float* __restrict__ bias, TOut* __restrict__ C, int Nc) {
    __shared__ uint32_t As[2048];   // 8KB
    __shared__ uint32_t Bs[2048];   // 8KB

    const int t = threadIdx.x;
    const int w = t >> 5;
    const int lane = t & 31;
    const int warp_m = w >> 2;
    const int warp_n = w & 3;
    const int mBase = blockIdx.y * 128;
    const int nBase = blockIdx.x * 128;

    const TIn* Ab = A + (size_t)mBase * 256;
    const bf16* Bb = Bt + (size_t)nBase * 256;

    float acc[4][4][4] = {};
    uint2 sa[4], sb[4];

    // stage loader: 4 consecutive k values -> two packed bf16x2 words
    auto loadA = [&](int row, int k) -> uint2 {
        if constexpr (sizeof(TIn) == 4) {
            float4 v = *(const float4*)(Ab + (size_t)row * 256 + k);
            return make_uint2(pk(v.x, v.y), pk(v.z, v.w));
        } else {
            return *(const uint2*)(Ab + (size_t)row * 256 + k);
        }
    };

#pragma unroll
    for (int r = 0; r < 4; r++) {
        int i = t + 256 * r;
        int row = i >> 3, k4 = i & 7;
        sa[r] = loadA(row, k4 * 4);
        sb[r] = *(const uint2*)(Bb + (size_t)row * 256 + k4 * 4);
    }

#pragma unroll 1
    for (int c = 0; c < 8; c++) {
        // store staged chunk into packed-fragment smem
#pragma unroll
        for (int r = 0; r < 4; r++) {
            int i = t + 256 * r;
            int row = i >> 3, k4 = i & 7;
            int kf = k4 >> 2;
            int p0 = (k4 & 3) * 2;           // even pair index 0,2,4,6
            int tq0 = p0 & 3, hi0 = p0 >> 2; // pair p0+1: tq0+1, same hi
            // A
            int mb = row >> 4, mr = row & 15, g = mr & 7, up = mr >> 3;
            uint32_t abase = ((uint32_t)(kf * 8 + mb) * 32 + g * 4) * 4 + up + 2 * hi0;
            As[abase + tq0 * 4]       = sa[r].x;
            As[abase + (tq0 + 1) * 4] = sa[r].y;
            // B
            int nb = row >> 3, nr = row & 7;
            uint32_t bbase = ((uint32_t)(kf * 16 + nb) * 32 + nr * 4) * 2 + hi0;
            Bs[bbase + tq0 * 2]       = sb[r].x;
            Bs[bbase + (tq0 + 1) * 2] = sb[r].y;
        }
        __syncthreads();

        if (c < 7) {
            int kc = (c + 1) * 32;
#pragma unroll
            for (int r = 0; r < 4; r++) {
                int i = t + 256 * r;
                int row = i >> 3, k4 = i & 7;
                sa[r] = loadA(row, kc + k4 * 4);
                sb[r] = *(const uint2*)(Bb + (size_t)row * 256 + kc + k4 * 4);
            }
        }

#pragma unroll
        for (int kf = 0; kf < 2; kf++) {
            uint4 av[4];
            uint2 bv[4];
#pragma unroll
            for (int mf = 0; mf < 4; mf++)
                av[mf] = *(const uint4*)&As[((kf * 8 + warp_m * 4 + mf) * 32 + lane) * 4];
#pragma unroll
            for (int nf = 0; nf < 4; nf++)
                bv[nf] = *(const uint2*)&Bs[((kf * 16 + warp_n * 4 + nf) * 32 + lane) * 2];
#pragma unroll
            for (int mf = 0; mf < 4; mf++)
#pragma unroll
                for (int nf = 0; nf < 4; nf++)
                    mma16(acc[mf][nf], av[mf], bv[nf]);
        }
        __syncthreads();
    }

    // epilogue
    const int g = lane >> 2;
    const int tq = lane & 3;
    float2 bz[4];
#pragma unroll
    for (int nf = 0; nf < 4; nf++)
        bz[nf] = *(const float2*)(bias + nBase + warp_n * 32 + nf * 8 + 2 * tq);

#pragma unroll
    for (int mf = 0; mf < 4; mf++) {
        int row0 = mBase + warp_m * 64 + mf * 16 + g;
#pragma unroll
        for (int nf = 0; nf < 4; nf++) {
            int col = nBase + warp_n * 32 + nf * 8 + 2 * tq;
            float v0 = acc[mf][nf][0] + bz[nf].x;
            float v1 = acc[mf][nf][1] + bz[nf].y;
            float v2 = acc[mf][nf][2] + bz[nf].x;
            float v3 = acc[mf][nf][3] + bz[nf].y;
            if constexpr (sizeof(TOut) == 2) {
                *(uint32_t*)(C + (size_t)row0 * Nc + col) = pk(v0, v1);
                *(uint32_t*)(C + (size_t)(row0 + 8) * Nc + col) = pk(v2, v3);
            } else {
                *(float2*)(C + (size_t)row0 * Nc + col) = make_float2(v0, v1);
                *(float2*)(C + (size_t)(row0 + 8) * Nc + col) = make_float2(v2, v3);
            }
        }
    }
}

// ---------------------------------------------------------------------------
// Tensor-core attention: one block per (b,h), 128 threads (4 warps).
// Warp w owns query rows 16w..16w+15.
//   S = Q K^T (bf16 MMA, fp32 acc) ; P = exp(S/16 + bias) (no max-sub:
//   scores bounded, identical softmax) ; O = P V via register-repacked P.
// ---------------------------------------------------------------------------
__global__ __launch_bounds__(128)
void attn_tc(const bf16* __restrict__ qkvQ, const bf16* __restrict__ qkvKV,
             const float* __restrict__ bias, bf16* __restrict__ out) {
    const int b = blockIdx.x;
    const int h = blockIdx.y;
    const int t = threadIdx.x;
    const int w = t >> 5;
    const int lane = t & 31;
    const int g = lane >> 2;
    const int tq = lane & 3;

    __shared__ bf16 Vs[64][40];    // padded rows: 80B, conflict-free ldsm

    // cooperative copy of V tile (64 x 32 bf16) into smem
    const bf16* base = qkvKV + (size_t)b * 64 * 768;
#pragma unroll
    for (int r = 0; r < 8; r++) {
        int i = t + 128 * r;           // 1024 u32 total
        int row = i >> 4, cc = i & 15; // 16 u32 per row
        *(uint32_t*)&Vs[row][cc * 2] =
            *(const uint32_t*)(base + (size_t)row * 768 + 512 + h * 32 + cc * 2);
    }
    __syncthreads();

    // Q A-fragments (direct LDG)
    const bf16* Qb = qkvQ + ((size_t)b * 64 + w * 16) * 768 + h * 32;
    uint4 aq[2];
#pragma unroll
    for (int kf = 0; kf < 2; kf++) {
        const bf16* p = Qb + kf * 16;
        aq[kf].x = *(const uint32_t*)(p + (size_t)g * 768 + 2 * tq);
        aq[kf].y = *(const uint32_t*)(p + (size_t)(g + 8) * 768 + 2 * tq);
        aq[kf].z = *(const uint32_t*)(p + (size_t)g * 768 + 2 * tq + 8);
        aq[kf].w = *(const uint32_t*)(p + (size_t)(g + 8) * 768 + 2 * tq + 8);
    }

    // S = Q K^T : K B-fragments direct LDG, 16 MMAs
    const bf16* Kb = base + 256 + h * 32;
    float s[8][4] = {};
#pragma unroll
    for (int nb = 0; nb < 8; nb++) {
        const bf16* kr = Kb + (size_t)(nb * 8 + g) * 768;
#pragma unroll
        for (int kf = 0; kf < 2; kf++) {
            uint2 bk;
            bk.x = *(const uint32_t*)(kr + kf * 16 + 2 * tq);
            bk.y = *(const uint32_t*)(kr + kf * 16 + 2 * tq + 8);
            mma16(s[nb], aq[kf], bk);
        }
    }

    // bias + exp + row sums
    const float* bb = bias + (size_t)h * 4096 + (size_t)(w * 16 + g) * 64;
    const float scale = 0.0625f;
    float slo = 0.0f, shi = 0.0f;
#pragma unroll
    for (int nf = 0; nf < 8; nf++) {
        float2 b0 = *(const float2*)(bb + nf * 8 + 2 * tq);
        float2 b1 = *(const float2*)(bb + 8 * 64 + nf * 8 + 2 * tq);
        s[nf][0] = __expf(s[nf][0] * scale + b0.x);
        s[nf][1] = __expf(s[nf][1] * scale + b0.y);
        s[nf][2] = __expf(s[nf][2] * scale + b1.x);
        s[nf][3] = __expf(s[nf][3] * scale + b1.y);
        slo += s[nf][0] + s[nf][1];
        shi += s[nf][2] + s[nf][3];
    }
    slo += __shfl_xor_sync(0xffffffffu, slo, 1);
    slo += __shfl_xor_sync(0xffffffffu, slo, 2);
    shi += __shfl_xor_sync(0xffffffffu, shi, 1);
    shi += __shfl_xor_sync(0xffffffffu, shi, 2);
    float il = 1.0f / slo, ih = 1.0f / shi;

    // O = P V : P accumulators repack directly into A-fragments
    float o[4][4] = {};
    uint32_t vbase = smem_u32(&Vs[0][0]) + (uint32_t)(lane & 15) * 80;
#pragma unroll
    for (int kf = 0; kf < 4; kf++) {
        uint4 ap;
        ap.x = pk(s[2 * kf][0], s[2 * kf][1]);
        ap.y = pk(s[2 * kf][2], s[2 * kf][3]);
        ap.z = pk(s[2 * kf + 1][0], s[2 * kf + 1][1]);
        ap.w = pk(s[2 * kf + 1][2], s[2 * kf + 1][3]);
        uint32_t rowaddr = vbase + (uint32_t)kf * 16 * 80;
#pragma unroll
        for (int nf = 0; nf < 4; nf++) {
            uint2 bv = ldsm_x2_trans(rowaddr + nf * 16);
            mma16(o[nf], ap, bv);
        }
    }

    // normalize + store bf16
    bf16* ob = out + ((size_t)b * 64 + w * 16) * 256 + h * 32;
#pragma unroll
    for (int nf = 0; nf < 4; nf++) {
        int col = nf * 8 + 2 * tq;
        *(uint32_t*)(ob + (size_t)g * 256 + col) = pk(o[nf][0] * il, o[nf][1] * il);
        *(uint32_t*)(ob + (size_t)(g + 8) * 256 + col) = pk(o[nf][2] * ih, o[nf][3] * ih);
    }
}

// ---------------------------------------------------------------------------
// Residual + LayerNorm: one warp per row of 256
// ---------------------------------------------------------------------------
__global__ __launch_bounds__(256)
void ln_kernel(const float* __restrict__ p, const float* __restrict__ resid,
               const float* __restrict__ g, const float* __restrict__ be,
               float* __restrict__ out) {
    int row = (blockIdx.x * blockDim.x + threadIdx.x) >> 5;
    int lane = threadIdx.x & 31;
    if (row >= Mrows) return;

    const float* pr = p + (size_t)row * 256;
    const float* rr = resid + (size_t)row * 256;

    float v[8];
    float s = 0.0f, sq = 0.0f;
#pragma unroll
    for (int j = 0; j < 8; j++) {
        float t = pr[lane + 32 * j] + rr[lane + 32 * j];
        v[j] = t;
        s += t;
        sq += t * t;
    }
#pragma unroll
    for (int o = 16; o; o >>= 1) {
        s += __shfl_xor_sync(0xffffffffu, s, o);
        sq += __shfl_xor_sync(0xffffffffu, sq, o);
    }
    float mean = s * (1.0f / 256.0f);
    float var = sq * (1.0f / 256.0f) - mean * mean;
    float r = rsqrtf(var + 1e-5f);

    float* orow = out + (size_t)row * 256;
#pragma unroll
    for (int j = 0; j < 8; j++) {
        int d = lane + 32 * j;
        orow[d] = (v[j] - mean) * r * g[d] + be[d];
    }
}

// ---------------------------------------------------------------------------
// launch
// ---------------------------------------------------------------------------
extern "C" void kernel_launch(void* const* d_in, const int* in_sizes, int n_in,
                              void* d_out, int out_size) {
    const float* x     = (const float*)d_in[0];
    const float* y     = (const float*)d_in[1];
    const float* Wqkv1 = (const float*)d_in[2];
    const float* bqkv1 = (const float*)d_in[3];
    const float* Wqkv2 = (const float*)d_in[4];
    const float* bqkv2 = (const float*)d_in[5];
    const float* bias1 = (const float*)d_in[6];
    const float* bias2 = (const float*)d_in[7];
    const float* Wp1   = (const float*)d_in[8];
    const float* bp1   = (const float*)d_in[9];
    const float* Wp2   = (const float*)d_in[10];
    const float* bp2   = (const float*)d_in[11];
    const float* g1    = (const float*)d_in[12];
    const float* be1   = (const float*)d_in[13];
    const float* g2    = (const float*)d_in[14];
    const float* be2   = (const float*)d_in[15];
    float* out = (float*)d_out;

    bf16 *qkv1, *qkv2, *o1, *o2, *wtq1, *wtq2, *wtp1, *wtp2;
    float *p1, *p2;
    cudaGetSymbolAddress((void**)&qkv1, g_qkv1);
    cudaGetSymbolAddress((void**)&qkv2, g_qkv2);
    cudaGetSymbolAddress((void**)&o1, g_o1);
    cudaGetSymbolAddress((void**)&o2, g_o2);
    cudaGetSymbolAddress((void**)&p1, g_p1);
    cudaGetSymbolAddress((void**)&p2, g_p2);
    cudaGetSymbolAddress((void**)&wtq1, g_wtq1);
    cudaGetSymbolAddress((void**)&wtq2, g_wtq2);
    cudaGetSymbolAddress((void**)&wtp1, g_wtp1);
    cudaGetSymbolAddress((void**)&wtp2, g_wtp2);

    // phase 0: transpose + bf16-round weights
    transpose_bf16<<<dim3(24, 8), dim3(32, 8)>>>(Wqkv1, wtq1, 768);
    transpose_bf16<<<dim3(24, 8), dim3(32, 8)>>>(Wqkv2, wtq2, 768);
    transpose_bf16<<<dim3(8, 8),  dim3(32, 8)>>>(Wp1,   wtp1, 256);
    transpose_bf16<<<dim3(8, 8),  dim3(32, 8)>>>(Wp2,   wtp2, 256);

    // phase 1: QKV projections (bf16 tensor pipe, bf16 output)
    dim3 gQKV(768 / 128, Mrows / 128);
    gemm_bf16<float, bf16><<<gQKV, 256>>>(x, wtq1, bqkv1, qkv1, 768);
    gemm_bf16<float, bf16><<<gQKV, 256>>>(y, wtq2, bqkv2, qkv2, 768);

    // phase 2: cross attention (tensor pipe)
    dim3 gA(Bwin, Hh);
    attn_tc<<<gA, 128>>>(qkv1, qkv2, bias1, o1);
    attn_tc<<<gA, 128>>>(qkv2, qkv1, bias2, o2);

    // phase 3: output projections (bf16 in, fp32 out)
    dim3 gP(256 / 128, Mrows / 128);
    gemm_bf16<bf16, float><<<gP, 256>>>(o1, wtp1, bp1, p1, 256);
    gemm_bf16<bf16, float><<<gP, 256>>>(o2, wtp2, bp2, p2, 256);

    // phase 4: residual + layernorm
    int lnBlocks = Mrows / 8;
    ln_kernel<<<lnBlocks, 256>>>(p1, x, g1, be1, out);
    ln_kernel<<<lnBlocks, 256>>>(p2, y, g2, be2, out + (size_t)Mrows * 256);
}

// round 5
// speedup vs baseline: 4.3904x; 1.0352x over previous
#include <cuda_runtime.h>
#include <cuda_bf16.h>
#include <math.h>
#include <stdint.h>

// ---------------------------------------------------------------------------
// WindowCrossAttention  B=4096, N=64, C=256, H=8, Dh=32
// Round 5: bf16 HMMA GEMMs + tensor-core attention + FUSED proj+residual+LN
// (64x256 CTA tile owns full rows -> CTA-local LN stats, no p round-trip).
// ---------------------------------------------------------------------------

#define Bwin 4096
#define Hh   8
#define Mrows (Bwin * 64)              // 262144

typedef __nv_bfloat16 bf16;

// scratch (static device arrays; no allocations allowed)
__device__ bf16  g_qkv1[(size_t)Mrows * 768];
__device__ bf16  g_qkv2[(size_t)Mrows * 768];
__device__ bf16  g_o1[(size_t)Mrows * 256];
__device__ bf16  g_o2[(size_t)Mrows * 256];
__device__ bf16  g_wtq1[768 * 256];
__device__ bf16  g_wtq2[768 * 256];
__device__ bf16  g_wtp1[256 * 256];
__device__ bf16  g_wtp2[256 * 256];

__device__ __forceinline__ uint32_t pk(float lo, float hi) {
    __nv_bfloat162 t = __float22bfloat162_rn(make_float2(lo, hi));
    return *reinterpret_cast<uint32_t*>(&t);
}
__device__ __forceinline__ uint32_t smem_u32(const void* p) {
    uint32_t a;
    asm("{ .reg .u64 t; cvta.to.shared.u64 t, %1; cvt.u32.u64 %0, t; }"
        : "=r"(a) : "l"(p));
    return a;
}

// m16n8k16 bf16 HMMA; canonical PTX register order.
__device__ __forceinline__ void mma16(float* c, uint4 a, uint2 b) {
    asm volatile(
        "mma.sync.aligned.m16n8k16.row.col.f32.bf16.bf16.f32 "
        "{%0,%1,%2,%3}, {%4,%5,%6,%7}, {%8,%9}, {%0,%1,%2,%3};"
        : "+f"(c[0]), "+f"(c[1]), "+f"(c[2]), "+f"(c[3])
        : "r"(a.x), "r"(a.y), "r"(a.z), "r"(a.w), "r"(b.x), "r"(b.y));
}

__device__ __forceinline__ uint2 ldsm_x2_trans(uint32_t addr) {
    uint2 r;
    asm volatile("ldmatrix.sync.aligned.m8n8.x2.trans.shared.b16 {%0,%1}, [%2];"
                 : "=r"(r.x), "=r"(r.y) : "r"(addr));
    return r;
}

// ---------------------------------------------------------------------------
// Weight transpose + bf16 round: W (256 x Nc) fp32 -> Wt (Nc x 256) bf16
// ---------------------------------------------------------------------------
__global__ void transpose_bf16(const float* __restrict__ W, bf16* __restrict__ Wt, int Nc) {
    __shared__ float tile[32][33];
    int n0 = blockIdx.x * 32;
    int k0 = blockIdx.y * 32;
    int tx = threadIdx.x, ty = threadIdx.y;   // (32, 8)
#pragma unroll
    for (int r = 0; r < 4; r++)
        tile[ty + 8 * r][tx] = W[(size_t)(k0 + ty + 8 * r) * Nc + n0 + tx];
    __syncthreads();
#pragma unroll
    for (int r = 0; r < 4; r++)
        Wt[(size_t)(n0 + ty + 8 * r) * 256 + k0 + tx] =
            __float2bfloat16_rn(tile[tx][ty + 8 * r]);
}

// ---------------------------------------------------------------------------
// bf16 HMMA GEMM (QKV): C(M x Nc) = A(M x 256) @ Wt^T + bias ; CTA 128x128
// ---------------------------------------------------------------------------
__global__ __launch_bounds__(256, 2)
void gemm_qkv(const float* __restrict__ A, const bf16* __restrict__ Bt,
              const float* __restrict__ bias, bf16* __restrict__ C, int Nc) {
    __shared__ uint32_t As[2048];
    __shared__ uint32_t Bs[2048];

    const int t = threadIdx.x;
    const int w = t >> 5;
    const int lane = t & 31;
    const int warp_m = w >> 2;
    const int warp_n = w & 3;
    const int mBase = blockIdx.y * 128;
    const int nBase = blockIdx.x * 128;

    const float* Ab = A + (size_t)mBase * 256;
    const bf16* Bb = Bt + (size_t)nBase * 256;

    float acc[4][4][4] = {};
    uint2 sa[4], sb[4];

#pragma unroll
    for (int r = 0; r < 4; r++) {
        int i = t + 256 * r;
        int row = i >> 3, k4 = i & 7;
        float4 v = *(const float4*)(Ab + (size_t)row * 256 + k4 * 4);
        sa[r] = make_uint2(pk(v.x, v.y), pk(v.z, v.w));
        sb[r] = *(const uint2*)(Bb + (size_t)row * 256 + k4 * 4);
    }

#pragma unroll 1
    for (int c = 0; c < 8; c++) {
#pragma unroll
        for (int r = 0; r < 4; r++) {
            int i = t + 256 * r;
            int row = i >> 3, k4 = i & 7;
            int kf = k4 >> 2;
            int p0 = (k4 & 3) * 2;
            int tq0 = p0 & 3, hi0 = p0 >> 2;
            int mb = row >> 4, mr = row & 15, g = mr & 7, up = mr >> 3;
            uint32_t abase = ((uint32_t)(kf * 8 + mb) * 32 + g * 4) * 4 + up + 2 * hi0;
            As[abase + tq0 * 4]       = sa[r].x;
            As[abase + (tq0 + 1) * 4] = sa[r].y;
            int nb = row >> 3, nr = row & 7;
            uint32_t bbase = ((uint32_t)(kf * 16 + nb) * 32 + nr * 4) * 2 + hi0;
            Bs[bbase + tq0 * 2]       = sb[r].x;
            Bs[bbase + (tq0 + 1) * 2] = sb[r].y;
        }
        __syncthreads();

        if (c < 7) {
            int kc = (c + 1) * 32;
#pragma unroll
            for (int r = 0; r < 4; r++) {
                int i = t + 256 * r;
                int row = i >> 3, k4 = i & 7;
                float4 v = *(const float4*)(Ab + (size_t)row * 256 + kc + k4 * 4);
                sa[r] = make_uint2(pk(v.x, v.y), pk(v.z, v.w));
                sb[r] = *(const uint2*)(Bb + (size_t)row * 256 + kc + k4 * 4);
            }
        }

#pragma unroll
        for (int kf = 0; kf < 2; kf++) {
            uint4 av[4];
            uint2 bv[4];
#pragma unroll
            for (int mf = 0; mf < 4; mf++)
                av[mf] = *(const uint4*)&As[((kf * 8 + warp_m * 4 + mf) * 32 + lane) * 4];
#pragma unroll
            for (int nf = 0; nf < 4; nf++)
                bv[nf] = *(const uint2*)&Bs[((kf * 16 + warp_n * 4 + nf) * 32 + lane) * 2];
#pragma unroll
            for (int mf = 0; mf < 4; mf++)
#pragma unroll
                for (int nf = 0; nf < 4; nf++)
                    mma16(acc[mf][nf], av[mf], bv[nf]);
        }
        __syncthreads();
    }

    const int g = lane >> 2;
    const int tq = lane & 3;
    float2 bz[4];
#pragma unroll
    for (int nf = 0; nf < 4; nf++)
        bz[nf] = *(const float2*)(bias + nBase + warp_n * 32 + nf * 8 + 2 * tq);

#pragma unroll
    for (int mf = 0; mf < 4; mf++) {
        int row0 = mBase + warp_m * 64 + mf * 16 + g;
#pragma unroll
        for (int nf = 0; nf < 4; nf++) {
            int col = nBase + warp_n * 32 + nf * 8 + 2 * tq;
            *(uint32_t*)(C + (size_t)row0 * Nc + col) =
                pk(acc[mf][nf][0] + bz[nf].x, acc[mf][nf][1] + bz[nf].y);
            *(uint32_t*)(C + (size_t)(row0 + 8) * Nc + col) =
                pk(acc[mf][nf][2] + bz[nf].x, acc[mf][nf][3] + bz[nf].y);
        }
    }
}

// ---------------------------------------------------------------------------
// FUSED proj + bias + residual + LayerNorm.
// CTA tile 64 rows x 256 cols (full width). 8 warps, warp tile 64x32
// (warp w owns cols [32w, 32w+32)). A fragments shared across warps.
// ---------------------------------------------------------------------------
__global__ __launch_bounds__(256, 2)
void proj_ln(const bf16* __restrict__ A, const bf16* __restrict__ Bt,
             const float* __restrict__ bias, const float* __restrict__ resid,
             const float* __restrict__ gamma, const float* __restrict__ beta,
             float* __restrict__ out) {
    __shared__ uint32_t As[1024];      // 4KB  [kf(2)][mb(4)][lane][4]
    __shared__ uint32_t Bs[4096];      // 16KB [kf(2)][nb(32)][lane][2]
    __shared__ float2 red[64][8];      // per-row (sum, sumsq) per warp
    __shared__ float2 mv[64];          // per-row (mean, rstd)

    const int t = threadIdx.x;
    const int w = t >> 5;              // warp_n 0..7
    const int lane = t & 31;
    const int g = lane >> 2;
    const int tq = lane & 3;
    const int mBase = blockIdx.x * 64;

    const bf16* Ab = A + (size_t)mBase * 256;

    float acc[4][4][4] = {};
    uint2 sa[2], sb[8];

#pragma unroll
    for (int r = 0; r < 2; r++) {
        int i = t + 256 * r;
        int row = i >> 3, k4 = i & 7;
        sa[r] = *(const uint2*)(Ab + (size_t)row * 256 + k4 * 4);
    }
#pragma unroll
    for (int r = 0; r < 8; r++) {
        int i = t + 256 * r;
        int row = i >> 3, k4 = i & 7;
        sb[r] = *(const uint2*)(Bt + (size_t)row * 256 + k4 * 4);
    }

#pragma unroll 1
    for (int c = 0; c < 8; c++) {
#pragma unroll
        for (int r = 0; r < 2; r++) {
            int i = t + 256 * r;
            int row = i >> 3, k4 = i & 7;
            int kf = k4 >> 2;
            int p0 = (k4 & 3) * 2;
            int tq0 = p0 & 3, hi0 = p0 >> 2;
            int mb = row >> 4, mr = row & 15, gg = mr & 7, up = mr >> 3;
            uint32_t abase = ((uint32_t)(kf * 4 + mb) * 32 + gg * 4) * 4 + up + 2 * hi0;
            As[abase + tq0 * 4]       = sa[r].x;
            As[abase + (tq0 + 1) * 4] = sa[r].y;
        }
#pragma unroll
        for (int r = 0; r < 8; r++) {
            int i = t + 256 * r;
            int row = i >> 3, k4 = i & 7;
            int kf = k4 >> 2;
            int p0 = (k4 & 3) * 2;
            int tq0 = p0 & 3, hi0 = p0 >> 2;
            int nb = row >> 3, nr = row & 7;
            uint32_t bbase = ((uint32_t)(kf * 32 + nb) * 32 + nr * 4) * 2 + hi0;
            Bs[bbase + tq0 * 2]       = sb[r].x;
            Bs[bbase + (tq0 + 1) * 2] = sb[r].y;
        }
        __syncthreads();

        if (c < 7) {
            int kc = (c + 1) * 32;
#pragma unroll
            for (int r = 0; r < 2; r++) {
                int i = t + 256 * r;
                int row = i >> 3, k4 = i & 7;
                sa[r] = *(const uint2*)(Ab + (size_t)row * 256 + kc + k4 * 4);
            }
#pragma unroll
            for (int r = 0; r < 8; r++) {
                int i = t + 256 * r;
                int row = i >> 3, k4 = i & 7;
                sb[r] = *(const uint2*)(Bt + (size_t)row * 256 + kc + k4 * 4);
            }
        }

#pragma unroll
        for (int kf = 0; kf < 2; kf++) {
            uint4 av[4];
            uint2 bv[4];
#pragma unroll
            for (int mf = 0; mf < 4; mf++)
                av[mf] = *(const uint4*)&As[((kf * 4 + mf) * 32 + lane) * 4];
#pragma unroll
            for (int nf = 0; nf < 4; nf++)
                bv[nf] = *(const uint2*)&Bs[((kf * 32 + w * 4 + nf) * 32 + lane) * 2];
#pragma unroll
            for (int mf = 0; mf < 4; mf++)
#pragma unroll
                for (int nf = 0; nf < 4; nf++)
                    mma16(acc[mf][nf], av[mf], bv[nf]);
        }
        __syncthreads();
    }

    // epilogue pass 1: val = acc + bias + resid (in place), row partials
    float2 bz[4];
#pragma unroll
    for (int nf = 0; nf < 4; nf++)
        bz[nf] = *(const float2*)(bias + w * 32 + nf * 8 + 2 * tq);

#pragma unroll
    for (int mf = 0; mf < 4; mf++) {
        int r0 = mf * 16 + g;
        float plo = 0.0f, phi = 0.0f, qlo = 0.0f, qhi = 0.0f;
#pragma unroll
        for (int nf = 0; nf < 4; nf++) {
            int col = w * 32 + nf * 8 + 2 * tq;
            float2 x0 = *(const float2*)(resid + (size_t)(mBase + r0) * 256 + col);
            float2 x1 = *(const float2*)(resid + (size_t)(mBase + r0 + 8) * 256 + col);
            float v0 = acc[mf][nf][0] + bz[nf].x + x0.x;
            float v1 = acc[mf][nf][1] + bz[nf].y + x0.y;
            float v2 = acc[mf][nf][2] + bz[nf].x + x1.x;
            float v3 = acc[mf][nf][3] + bz[nf].y + x1.y;
            acc[mf][nf][0] = v0; acc[mf][nf][1] = v1;
            acc[mf][nf][2] = v2; acc[mf][nf][3] = v3;
            plo += v0 + v1; phi += v2 + v3;
            qlo += v0 * v0 + v1 * v1; qhi += v2 * v2 + v3 * v3;
        }
        plo += __shfl_xor_sync(0xffffffffu, plo, 1);
        plo += __shfl_xor_sync(0xffffffffu, plo, 2);
        qlo += __shfl_xor_sync(0xffffffffu, qlo, 1);
        qlo += __shfl_xor_sync(0xffffffffu, qlo, 2);
        phi += __shfl_xor_sync(0xffffffffu, phi, 1);
        phi += __shfl_xor_sync(0xffffffffu, phi, 2);
        qhi += __shfl_xor_sync(0xffffffffu, qhi, 1);
        qhi += __shfl_xor_sync(0xffffffffu, qhi, 2);
        if (tq == 0) {
            red[r0][w]     = make_float2(plo, qlo);
            red[r0 + 8][w] = make_float2(phi, qhi);
        }
    }
    __syncthreads();

    if (t < 64) {
        float s = 0.0f, q = 0.0f;
#pragma unroll
        for (int j = 0; j < 8; j++) { s += red[t][j].x; q += red[t][j].y; }
        float mean = s * (1.0f / 256.0f);
        float var = q * (1.0f / 256.0f) - mean * mean;
        mv[t] = make_float2(mean, rsqrtf(var + 1e-5f));
    }
    __syncthreads();

    // epilogue pass 2: normalize + affine + store
#pragma unroll
    for (int nf = 0; nf < 4; nf++) {
        int col = w * 32 + nf * 8 + 2 * tq;
        float2 gm = *(const float2*)(gamma + col);
        float2 bt = *(const float2*)(beta + col);
#pragma unroll
        for (int mf = 0; mf < 4; mf++) {
            int r0 = mf * 16 + g;
            float2 m0 = mv[r0];
            float2 m1 = mv[r0 + 8];
            float2 o0 = { (acc[mf][nf][0] - m0.x) * m0.y * gm.x + bt.x,
                          (acc[mf][nf][1] - m0.x) * m0.y * gm.y + bt.y };
            float2 o1 = { (acc[mf][nf][2] - m1.x) * m1.y * gm.x + bt.x,
                          (acc[mf][nf][3] - m1.x) * m1.y * gm.y + bt.y };
            *(float2*)(out + (size_t)(mBase + r0) * 256 + col) = o0;
            *(float2*)(out + (size_t)(mBase + r0 + 8) * 256 + col) = o1;
        }
    }
}

// ---------------------------------------------------------------------------
// Tensor-core attention: one block per (b,h), 128 threads (4 warps).
// ---------------------------------------------------------------------------
__global__ __launch_bounds__(128)
void attn_tc(const bf16* __restrict__ qkvQ, const bf16* __restrict__ qkvKV,
             const float* __restrict__ bias, bf16* __restrict__ out) {
    const int b = blockIdx.x;
    const int h = blockIdx.y;
    const int t = threadIdx.x;
    const int w = t >> 5;
    const int lane = t & 31;
    const int g = lane >> 2;
    const int tq = lane & 3;

    __shared__ bf16 Vs[64][40];

    const bf16* base = qkvKV + (size_t)b * 64 * 768;
#pragma unroll
    for (int r = 0; r < 8; r++) {
        int i = t + 128 * r;
        int row = i >> 4, cc = i & 15;
        *(uint32_t*)&Vs[row][cc * 2] =
            *(const uint32_t*)(base + (size_t)row * 768 + 512 + h * 32 + cc * 2);
    }
    __syncthreads();

    const bf16* Qb = qkvQ + ((size_t)b * 64 + w * 16) * 768 + h * 32;
    uint4 aq[2];
#pragma unroll
    for (int kf = 0; kf < 2; kf++) {
        const bf16* p = Qb + kf * 16;
        aq[kf].x = *(const uint32_t*)(p + (size_t)g * 768 + 2 * tq);
        aq[kf].y = *(const uint32_t*)(p + (size_t)(g + 8) * 768 + 2 * tq);
        aq[kf].z = *(const uint32_t*)(p + (size_t)g * 768 + 2 * tq + 8);
        aq[kf].w = *(const uint32_t*)(p + (size_t)(g + 8) * 768 + 2 * tq + 8);
    }

    const bf16* Kb = base + 256 + h * 32;
    float s[8][4] = {};
#pragma unroll
    for (int nb = 0; nb < 8; nb++) {
        const bf16* kr = Kb + (size_t)(nb * 8 + g) * 768;
#pragma unroll
        for (int kf = 0; kf < 2; kf++) {
            uint2 bk;
            bk.x = *(const uint32_t*)(kr + kf * 16 + 2 * tq);
            bk.y = *(const uint32_t*)(kr + kf * 16 + 2 * tq + 8);
            mma16(s[nb], aq[kf], bk);
        }
    }

    const float* bb = bias + (size_t)h * 4096 + (size_t)(w * 16 + g) * 64;
    const float scale = 0.0625f;
    float slo = 0.0f, shi = 0.0f;
#pragma unroll
    for (int nf = 0; nf < 8; nf++) {
        float2 b0 = *(const float2*)(bb + nf * 8 + 2 * tq);
        float2 b1 = *(const float2*)(bb + 8 * 64 + nf * 8 + 2 * tq);
        s[nf][0] = __expf(s[nf][0] * scale + b0.x);
        s[nf][1] = __expf(s[nf][1] * scale + b0.y);
        s[nf][2] = __expf(s[nf][2] * scale + b1.x);
        s[nf][3] = __expf(s[nf][3] * scale + b1.y);
        slo += s[nf][0] + s[nf][1];
        shi += s[nf][2] + s[nf][3];
    }
    slo += __shfl_xor_sync(0xffffffffu, slo, 1);
    slo += __shfl_xor_sync(0xffffffffu, slo, 2);
    shi += __shfl_xor_sync(0xffffffffu, shi, 1);
    shi += __shfl_xor_sync(0xffffffffu, shi, 2);
    float il = 1.0f / slo, ih = 1.0f / shi;

    float o[4][4] = {};
    uint32_t vbase = smem_u32(&Vs[0][0]) + (uint32_t)(lane & 15) * 80;
#pragma unroll
    for (int kf = 0; kf < 4; kf++) {
        uint4 ap;
        ap.x = pk(s[2 * kf][0], s[2 * kf][1]);
        ap.y = pk(s[2 * kf][2], s[2 * kf][3]);
        ap.z = pk(s[2 * kf + 1][0], s[2 * kf + 1][1]);
        ap.w = pk(s[2 * kf + 1][2], s[2 * kf + 1][3]);
        uint32_t rowaddr = vbase + (uint32_t)kf * 16 * 80;
#pragma unroll
        for (int nf = 0; nf < 4; nf++) {
            uint2 bv = ldsm_x2_trans(rowaddr + nf * 16);
            mma16(o[nf], ap, bv);
        }
    }

    bf16* ob = out + ((size_t)b * 64 + w * 16) * 256 + h * 32;
#pragma unroll
    for (int nf = 0; nf < 4; nf++) {
        int col = nf * 8 + 2 * tq;
        *(uint32_t*)(ob + (size_t)g * 256 + col) = pk(o[nf][0] * il, o[nf][1] * il);
        *(uint32_t*)(ob + (size_t)(g + 8) * 256 + col) = pk(o[nf][2] * ih, o[nf][3] * ih);
    }
}

// ---------------------------------------------------------------------------
// launch
// ---------------------------------------------------------------------------
extern "C" void kernel_launch(void* const* d_in, const int* in_sizes, int n_in,
                              void* d_out, int out_size) {
    const float* x     = (const float*)d_in[0];
    const float* y     = (const float*)d_in[1];
    const float* Wqkv1 = (const float*)d_in[2];
    const float* bqkv1 = (const float*)d_in[3];
    const float* Wqkv2 = (const float*)d_in[4];
    const float* bqkv2 = (const float*)d_in[5];
    const float* bias1 = (const float*)d_in[6];
    const float* bias2 = (const float*)d_in[7];
    const float* Wp1   = (const float*)d_in[8];
    const float* bp1   = (const float*)d_in[9];
    const float* Wp2   = (const float*)d_in[10];
    const float* bp2   = (const float*)d_in[11];
    const float* g1    = (const float*)d_in[12];
    const float* be1   = (const float*)d_in[13];
    const float* g2    = (const float*)d_in[14];
    const float* be2   = (const float*)d_in[15];
    float* out = (float*)d_out;

    bf16 *qkv1, *qkv2, *o1, *o2, *wtq1, *wtq2, *wtp1, *wtp2;
    cudaGetSymbolAddress((void**)&qkv1, g_qkv1);
    cudaGetSymbolAddress((void**)&qkv2, g_qkv2);
    cudaGetSymbolAddress((void**)&o1, g_o1);
    cudaGetSymbolAddress((void**)&o2, g_o2);
    cudaGetSymbolAddress((void**)&wtq1, g_wtq1);
    cudaGetSymbolAddress((void**)&wtq2, g_wtq2);
    cudaGetSymbolAddress((void**)&wtp1, g_wtp1);
    cudaGetSymbolAddress((void**)&wtp2, g_wtp2);

    // phase 0: transpose + bf16-round weights
    transpose_bf16<<<dim3(24, 8), dim3(32, 8)>>>(Wqkv1, wtq1, 768);
    transpose_bf16<<<dim3(24, 8), dim3(32, 8)>>>(Wqkv2, wtq2, 768);
    transpose_bf16<<<dim3(8, 8),  dim3(32, 8)>>>(Wp1,   wtp1, 256);
    transpose_bf16<<<dim3(8, 8),  dim3(32, 8)>>>(Wp2,   wtp2, 256);

    // phase 1: QKV projections
    dim3 gQKV(768 / 128, Mrows / 128);
    gemm_qkv<<<gQKV, 256>>>(x, wtq1, bqkv1, qkv1, 768);
    gemm_qkv<<<gQKV, 256>>>(y, wtq2, bqkv2, qkv2, 768);

    // phase 2: cross attention
    dim3 gA(Bwin, Hh);
    attn_tc<<<gA, 128>>>(qkv1, qkv2, bias1, o1);
    attn_tc<<<gA, 128>>>(qkv2, qkv1, bias2, o2);

    // phase 3+4: fused proj + residual + LayerNorm
    proj_ln<<<Mrows / 64, 256>>>(o1, wtp1, bp1, x, g1, be1, out);
    proj_ln<<<Mrows / 64, 256>>>(o2, wtp2, bp2, y, g2, be2, out + (size_t)Mrows * 256);
}

// round 6
// speedup vs baseline: 5.2286x; 1.1909x over previous
#include <cuda_runtime.h>
#include <cuda_bf16.h>
#include <math.h>
#include <stdint.h>

// ---------------------------------------------------------------------------
// WindowCrossAttention  B=4096, N=64, C=256, H=8, Dh=32
// Round 6: ldmatrix + double-buffered bf16 HMMA mainloops (80B-padded rows,
// conflict-free), K via ldmatrix in attention, merged launches via grid.z.
// ---------------------------------------------------------------------------

#define Bwin 4096
#define Hh   8
#define Mrows (Bwin * 64)              // 262144

typedef __nv_bfloat16 bf16;

// scratch (static device arrays; no allocations allowed)
__device__ bf16  g_qkv1[(size_t)Mrows * 768];
__device__ bf16  g_qkv2[(size_t)Mrows * 768];
__device__ bf16  g_o1[(size_t)Mrows * 256];
__device__ bf16  g_o2[(size_t)Mrows * 256];
__device__ bf16  g_wtq1[768 * 256];
__device__ bf16  g_wtq2[768 * 256];
__device__ bf16  g_wtp1[256 * 256];
__device__ bf16  g_wtp2[256 * 256];

__device__ __forceinline__ uint32_t pk(float lo, float hi) {
    __nv_bfloat162 t = __float22bfloat162_rn(make_float2(lo, hi));
    return *reinterpret_cast<uint32_t*>(&t);
}
__device__ __forceinline__ uint32_t smem_u32(const void* p) {
    uint32_t a;
    asm("{ .reg .u64 t; cvta.to.shared.u64 t, %1; cvt.u32.u64 %0, t; }"
        : "=r"(a) : "l"(p));
    return a;
}

__device__ __forceinline__ void mma16(float* c, uint4 a, uint2 b) {
    asm volatile(
        "mma.sync.aligned.m16n8k16.row.col.f32.bf16.bf16.f32 "
        "{%0,%1,%2,%3}, {%4,%5,%6,%7}, {%8,%9}, {%0,%1,%2,%3};"
        : "+f"(c[0]), "+f"(c[1]), "+f"(c[2]), "+f"(c[3])
        : "r"(a.x), "r"(a.y), "r"(a.z), "r"(a.w), "r"(b.x), "r"(b.y));
}
__device__ __forceinline__ uint4 ldsm_x4(uint32_t addr) {
    uint4 r;
    asm volatile("ldmatrix.sync.aligned.m8n8.x4.shared.b16 {%0,%1,%2,%3}, [%4];"
                 : "=r"(r.x), "=r"(r.y), "=r"(r.z), "=r"(r.w) : "r"(addr));
    return r;
}
__device__ __forceinline__ uint2 ldsm_x2_trans(uint32_t addr) {
    uint2 r;
    asm volatile("ldmatrix.sync.aligned.m8n8.x2.trans.shared.b16 {%0,%1}, [%2];"
                 : "=r"(r.x), "=r"(r.y) : "r"(addr));
    return r;
}

// row stride of padded smem tiles: 40 bf16 = 80B = 5 x 16B granules
#define RP 40
#define RPB 80

// ---------------------------------------------------------------------------
// Weight transposes (all four in one launch, z selects)
// ---------------------------------------------------------------------------
__global__ void transpose_all(const float* __restrict__ Wq1, bf16* __restrict__ Tq1,
                              const float* __restrict__ Wq2, bf16* __restrict__ Tq2,
                              const float* __restrict__ Wp1, bf16* __restrict__ Tp1,
                              const float* __restrict__ Wp2, bf16* __restrict__ Tp2) {
    const float* W;
    bf16* Wt;
    int Nc;
    switch (blockIdx.z) {
        case 0: W = Wq1; Wt = Tq1; Nc = 768; break;
        case 1: W = Wq2; Wt = Tq2; Nc = 768; break;
        case 2: W = Wp1; Wt = Tp1; Nc = 256; break;
        default: W = Wp2; Wt = Tp2; Nc = 256; break;
    }
    if (blockIdx.x * 32 >= Nc) return;
    __shared__ float tile[32][33];
    int n0 = blockIdx.x * 32;
    int k0 = blockIdx.y * 32;
    int tx = threadIdx.x, ty = threadIdx.y;   // (32, 8)
#pragma unroll
    for (int r = 0; r < 4; r++)
        tile[ty + 8 * r][tx] = W[(size_t)(k0 + ty + 8 * r) * Nc + n0 + tx];
    __syncthreads();
#pragma unroll
    for (int r = 0; r < 4; r++)
        Wt[(size_t)(n0 + ty + 8 * r) * 256 + k0 + tx] =
            __float2bfloat16_rn(tile[tx][ty + 8 * r]);
}

// ---------------------------------------------------------------------------
// QKV GEMM: C(M x 768) = A(M x 256 fp32) @ Wt^T + bias ; CTA 128x128,
// 8 warps (2m x 4n), warp 64x32, BK=32, double-buffered ldmatrix smem.
// grid.z selects direction.
// ---------------------------------------------------------------------------
__global__ __launch_bounds__(256, 2)
void gemm_qkv(const float* __restrict__ x, const float* __restrict__ y,
              const bf16* __restrict__ wt1, const bf16* __restrict__ wt2,
              const float* __restrict__ bq1, const float* __restrict__ bq2,
              bf16* __restrict__ c1, bf16* __restrict__ c2) {
    __shared__ __align__(16) bf16 As[2][128][RP];
    __shared__ __align__(16) bf16 Bs[2][128][RP];
    const int Nc = 768;

    const float* A   = blockIdx.z ? y : x;
    const bf16* Bt   = blockIdx.z ? wt2 : wt1;
    const float* bias = blockIdx.z ? bq2 : bq1;
    bf16* C          = blockIdx.z ? c2 : c1;

    const int t = threadIdx.x;
    const int w = t >> 5, lane = t & 31;
    const int warp_m = w >> 2, warp_n = w & 3;
    const int mBase = blockIdx.y * 128, nBase = blockIdx.x * 128;

    const float* Ab = A + (size_t)mBase * 256;
    const bf16*  Bb = Bt + (size_t)nBase * 256;

    // loader coords: 2 granules per thread per tile
    const int lr = t >> 2;      // row 0..63 (+64 for second)
    const int lg = t & 3;       // 16B granule within 64B of data

    float4 alo[2], ahi[2];
    uint4 bst[2];
    auto LDG = [&](int kc) {
#pragma unroll
        for (int rr = 0; rr < 2; rr++) {
            const float* p = Ab + (size_t)(lr + rr * 64) * 256 + kc + lg * 8;
            alo[rr] = *(const float4*)p;
            ahi[rr] = *(const float4*)(p + 4);
            bst[rr] = *(const uint4*)(Bb + (size_t)(lr + rr * 64) * 256 + kc + lg * 8);
        }
    };
    auto STS = [&](int buf) {
#pragma unroll
        for (int rr = 0; rr < 2; rr++) {
            uint4 pa = { pk(alo[rr].x, alo[rr].y), pk(alo[rr].z, alo[rr].w),
                         pk(ahi[rr].x, ahi[rr].y), pk(ahi[rr].z, ahi[rr].w) };
            *(uint4*)&As[buf][lr + rr * 64][lg * 8] = pa;
            *(uint4*)&Bs[buf][lr + rr * 64][lg * 8] = bst[rr];
        }
    };

    // per-lane ldmatrix address components
    uint32_t a_base = smem_u32(&As[0][0][0]) +
        (uint32_t)(warp_m * 64 + (lane & 15)) * RPB + (uint32_t)(lane >> 4) * 16;
    uint32_t b_base = smem_u32(&Bs[0][0][0]) +
        (uint32_t)(warp_n * 32 + (lane & 7) + ((lane >> 4) & 1) * 8) * RPB +
        (uint32_t)((lane >> 3) & 1) * 16;

    float acc[4][4][4] = {};

    LDG(0);
    STS(0);
    __syncthreads();

#pragma unroll 1
    for (int c = 0; c < 8; c++) {
        if (c < 7) LDG((c + 1) * 32);
        const uint32_t ab = a_base + (uint32_t)(c & 1) * (128 * RPB);
        const uint32_t bb = b_base + (uint32_t)(c & 1) * (128 * RPB);
#pragma unroll
        for (int kf = 0; kf < 2; kf++) {
            uint4 av[4];
#pragma unroll
            for (int mf = 0; mf < 4; mf++)
                av[mf] = ldsm_x4(ab + (uint32_t)mf * 16 * RPB + (uint32_t)kf * 32);
            uint4 bp0 = ldsm_x4(bb + (uint32_t)kf * 32);
            uint4 bp1 = ldsm_x4(bb + 16 * RPB + (uint32_t)kf * 32);
            uint2 bv[4] = { {bp0.x, bp0.y}, {bp0.z, bp0.w},
                            {bp1.x, bp1.y}, {bp1.z, bp1.w} };
#pragma unroll
            for (int mf = 0; mf < 4; mf++)
#pragma unroll
                for (int nf = 0; nf < 4; nf++)
                    mma16(acc[mf][nf], av[mf], bv[nf]);
        }
        if (c < 7) {
            STS((c + 1) & 1);
            __syncthreads();
        }
    }

    // epilogue: bias add + bf16 store
    const int g = lane >> 2;
    const int tq = lane & 3;
    float2 bz[4];
#pragma unroll
    for (int nf = 0; nf < 4; nf++)
        bz[nf] = *(const float2*)(bias + nBase + warp_n * 32 + nf * 8 + 2 * tq);

#pragma unroll
    for (int mf = 0; mf < 4; mf++) {
        int row0 = mBase + warp_m * 64 + mf * 16 + g;
#pragma unroll
        for (int nf = 0; nf < 4; nf++) {
            int col = nBase + warp_n * 32 + nf * 8 + 2 * tq;
            *(uint32_t*)(C + (size_t)row0 * Nc + col) =
                pk(acc[mf][nf][0] + bz[nf].x, acc[mf][nf][1] + bz[nf].y);
            *(uint32_t*)(C + (size_t)(row0 + 8) * Nc + col) =
                pk(acc[mf][nf][2] + bz[nf].x, acc[mf][nf][3] + bz[nf].y);
        }
    }
}

// ---------------------------------------------------------------------------
// FUSED proj + bias + residual + LayerNorm.  CTA 64 x 256 (full rows),
// 8 warps n-split, warp 64x32, BK=32, ldmatrix double-buffered. grid.z = dir.
// ---------------------------------------------------------------------------
__global__ __launch_bounds__(256, 2)
void proj_ln(const bf16* __restrict__ o1, const bf16* __restrict__ o2,
             const bf16* __restrict__ wt1, const bf16* __restrict__ wt2,
             const float* __restrict__ bp1, const float* __restrict__ bp2,
             const float* __restrict__ x, const float* __restrict__ y,
             const float* __restrict__ g1, const float* __restrict__ be1,
             const float* __restrict__ g2, const float* __restrict__ be2,
             float* __restrict__ outbase) {
    __shared__ __align__(16) bf16 As[2][64][RP];
    __shared__ __align__(16) bf16 Bs[2][256][RP];
    __shared__ float2 red[64][8];
    __shared__ float2 mv[64];

    const bf16* A     = blockIdx.z ? o2 : o1;
    const bf16* Bt    = blockIdx.z ? wt2 : wt1;
    const float* bias = blockIdx.z ? bp2 : bp1;
    const float* resid = blockIdx.z ? y : x;
    const float* gamma = blockIdx.z ? g2 : g1;
    const float* beta  = blockIdx.z ? be2 : be1;
    float* out = outbase + (size_t)blockIdx.z * Mrows * 256;

    const int t = threadIdx.x;
    const int w = t >> 5, lane = t & 31;
    const int g = lane >> 2, tq = lane & 3;
    const int mBase = blockIdx.x * 64;

    const bf16* Ab = A + (size_t)mBase * 256;

    const int lr = t >> 2;     // A row 0..63 / B row (+64,128,192)
    const int lg = t & 3;

    uint4 ast;
    uint4 bst[4];
    auto LDG = [&](int kc) {
        ast = *(const uint4*)(Ab + (size_t)lr * 256 + kc + lg * 8);
#pragma unroll
        for (int rr = 0; rr < 4; rr++)
            bst[rr] = *(const uint4*)(Bt + (size_t)(lr + rr * 64) * 256 + kc + lg * 8);
    };
    auto STS = [&](int buf) {
        *(uint4*)&As[buf][lr][lg * 8] = ast;
#pragma unroll
        for (int rr = 0; rr < 4; rr++)
            *(uint4*)&Bs[buf][lr + rr * 64][lg * 8] = bst[rr];
    };

    uint32_t a_base = smem_u32(&As[0][0][0]) +
        (uint32_t)(lane & 15) * RPB + (uint32_t)(lane >> 4) * 16;
    uint32_t b_base = smem_u32(&Bs[0][0][0]) +
        (uint32_t)(w * 32 + (lane & 7) + ((lane >> 4) & 1) * 8) * RPB +
        (uint32_t)((lane >> 3) & 1) * 16;

    float acc[4][4][4] = {};

    LDG(0);
    STS(0);
    __syncthreads();

#pragma unroll 1
    for (int c = 0; c < 8; c++) {
        if (c < 7) LDG((c + 1) * 32);
        const uint32_t ab = a_base + (uint32_t)(c & 1) * (64 * RPB);
        const uint32_t bb = b_base + (uint32_t)(c & 1) * (256 * RPB);
#pragma unroll
        for (int kf = 0; kf < 2; kf++) {
            uint4 av[4];
#pragma unroll
            for (int mf = 0; mf < 4; mf++)
                av[mf] = ldsm_x4(ab + (uint32_t)mf * 16 * RPB + (uint32_t)kf * 32);
            uint4 bp0 = ldsm_x4(bb + (uint32_t)kf * 32);
            uint4 bp1 = ldsm_x4(bb + 16 * RPB + (uint32_t)kf * 32);
            uint2 bv[4] = { {bp0.x, bp0.y}, {bp0.z, bp0.w},
                            {bp1.x, bp1.y}, {bp1.z, bp1.w} };
#pragma unroll
            for (int mf = 0; mf < 4; mf++)
#pragma unroll
                for (int nf = 0; nf < 4; nf++)
                    mma16(acc[mf][nf], av[mf], bv[nf]);
        }
        if (c < 7) {
            STS((c + 1) & 1);
            __syncthreads();
        }
    }

    // epilogue pass 1: val = acc + bias + resid, per-row partial stats
    float2 bz[4];
#pragma unroll
    for (int nf = 0; nf < 4; nf++)
        bz[nf] = *(const float2*)(bias + w * 32 + nf * 8 + 2 * tq);

#pragma unroll
    for (int mf = 0; mf < 4; mf++) {
        int r0 = mf * 16 + g;
        float plo = 0.0f, phi = 0.0f, qlo = 0.0f, qhi = 0.0f;
#pragma unroll
        for (int nf = 0; nf < 4; nf++) {
            int col = w * 32 + nf * 8 + 2 * tq;
            float2 x0 = *(const float2*)(resid + (size_t)(mBase + r0) * 256 + col);
            float2 x1 = *(const float2*)(resid + (size_t)(mBase + r0 + 8) * 256 + col);
            float v0 = acc[mf][nf][0] + bz[nf].x + x0.x;
            float v1 = acc[mf][nf][1] + bz[nf].y + x0.y;
            float v2 = acc[mf][nf][2] + bz[nf].x + x1.x;
            float v3 = acc[mf][nf][3] + bz[nf].y + x1.y;
            acc[mf][nf][0] = v0; acc[mf][nf][1] = v1;
            acc[mf][nf][2] = v2; acc[mf][nf][3] = v3;
            plo += v0 + v1; phi += v2 + v3;
            qlo += v0 * v0 + v1 * v1; qhi += v2 * v2 + v3 * v3;
        }
        plo += __shfl_xor_sync(0xffffffffu, plo, 1);
        plo += __shfl_xor_sync(0xffffffffu, plo, 2);
        qlo += __shfl_xor_sync(0xffffffffu, qlo, 1);
        qlo += __shfl_xor_sync(0xffffffffu, qlo, 2);
        phi += __shfl_xor_sync(0xffffffffu, phi, 1);
        phi += __shfl_xor_sync(0xffffffffu, phi, 2);
        qhi += __shfl_xor_sync(0xffffffffu, qhi, 1);
        qhi += __shfl_xor_sync(0xffffffffu, qhi, 2);
        if (tq == 0) {
            red[r0][w]     = make_float2(plo, qlo);
            red[r0 + 8][w] = make_float2(phi, qhi);
        }
    }
    __syncthreads();

    if (t < 64) {
        float s = 0.0f, q = 0.0f;
#pragma unroll
        for (int j = 0; j < 8; j++) { s += red[t][j].x; q += red[t][j].y; }
        float mean = s * (1.0f / 256.0f);
        float var = q * (1.0f / 256.0f) - mean * mean;
        mv[t] = make_float2(mean, rsqrtf(var + 1e-5f));
    }
    __syncthreads();

    // epilogue pass 2: normalize + affine + store
#pragma unroll
    for (int nf = 0; nf < 4; nf++) {
        int col = w * 32 + nf * 8 + 2 * tq;
        float2 gm = *(const float2*)(gamma + col);
        float2 bt = *(const float2*)(beta + col);
#pragma unroll
        for (int mf = 0; mf < 4; mf++) {
            int r0 = mf * 16 + g;
            float2 m0 = mv[r0];
            float2 m1 = mv[r0 + 8];
            float2 u0 = { (acc[mf][nf][0] - m0.x) * m0.y * gm.x + bt.x,
                          (acc[mf][nf][1] - m0.x) * m0.y * gm.y + bt.y };
            float2 u1 = { (acc[mf][nf][2] - m1.x) * m1.y * gm.x + bt.x,
                          (acc[mf][nf][3] - m1.x) * m1.y * gm.y + bt.y };
            *(float2*)(out + (size_t)(mBase + r0) * 256 + col) = u0;
            *(float2*)(out + (size_t)(mBase + r0 + 8) * 256 + col) = u1;
        }
    }
}

// ---------------------------------------------------------------------------
// Tensor-core attention: block per (b,h), 128 threads (4 warps), grid.z = dir.
// K and V staged in smem; K fragments via ldmatrix, V via ldmatrix.trans.
// ---------------------------------------------------------------------------
__global__ __launch_bounds__(128)
void attn_tc(const bf16* __restrict__ qkv1, const bf16* __restrict__ qkv2,
             const float* __restrict__ bias1, const float* __restrict__ bias2,
             bf16* __restrict__ o1, bf16* __restrict__ o2) {
    const bf16* qkvQ  = blockIdx.z ? qkv2 : qkv1;
    const bf16* qkvKV = blockIdx.z ? qkv1 : qkv2;
    const float* bias = blockIdx.z ? bias2 : bias1;
    bf16* out         = blockIdx.z ? o2 : o1;

    const int b = blockIdx.x;
    const int h = blockIdx.y;
    const int t = threadIdx.x;
    const int w = t >> 5;
    const int lane = t & 31;
    const int g = lane >> 2;
    const int tq = lane & 3;

    __shared__ __align__(16) bf16 Ks[64][RP];
    __shared__ __align__(16) bf16 Vs[64][RP];

    // cooperative 16B-granule loads of K and V (64 x 32 each)
    const bf16* base = qkvKV + (size_t)b * 64 * 768;
    {
        const int lr = t >> 2, lg = t & 3;   // 128 threads x 2 = 256 granules
#pragma unroll
        for (int rr = 0; rr < 2; rr++) {
            int row = lr + rr * 32;
            const bf16* src = base + (size_t)row * 768 + h * 32 + lg * 8;
            *(uint4*)&Ks[row][lg * 8] = *(const uint4*)(src + 256);
            *(uint4*)&Vs[row][lg * 8] = *(const uint4*)(src + 512);
        }
    }
    __syncthreads();

    // Q A-fragments (direct LDG)
    const bf16* Qb = qkvQ + ((size_t)b * 64 + w * 16) * 768 + h * 32;
    uint4 aq[2];
#pragma unroll
    for (int kf = 0; kf < 2; kf++) {
        const bf16* p = Qb + kf * 16;
        aq[kf].x = *(const uint32_t*)(p + (size_t)g * 768 + 2 * tq);
        aq[kf].y = *(const uint32_t*)(p + (size_t)(g + 8) * 768 + 2 * tq);
        aq[kf].z = *(const uint32_t*)(p + (size_t)g * 768 + 2 * tq + 8);
        aq[kf].w = *(const uint32_t*)(p + (size_t)(g + 8) * 768 + 2 * tq + 8);
    }

    // S = Q K^T via ldmatrix B fragments
    uint32_t k_base = smem_u32(&Ks[0][0]) +
        (uint32_t)((lane & 7) + ((lane >> 4) & 1) * 8) * RPB +
        (uint32_t)((lane >> 3) & 1) * 16;
    float s[8][4] = {};
#pragma unroll
    for (int p = 0; p < 4; p++) {
        uint32_t pa = k_base + (uint32_t)p * 16 * RPB;
#pragma unroll
        for (int kf = 0; kf < 2; kf++) {
            uint4 bp = ldsm_x4(pa + (uint32_t)kf * 32);
            mma16(s[2 * p],     aq[kf], make_uint2(bp.x, bp.y));
            mma16(s[2 * p + 1], aq[kf], make_uint2(bp.z, bp.w));
        }
    }

    // bias + exp + row sums
    const float* bb = bias + (size_t)h * 4096 + (size_t)(w * 16 + g) * 64;
    const float scale = 0.0625f;
    float slo = 0.0f, shi = 0.0f;
#pragma unroll
    for (int nf = 0; nf < 8; nf++) {
        float2 b0 = *(const float2*)(bb + nf * 8 + 2 * tq);
        float2 b1 = *(const float2*)(bb + 8 * 64 + nf * 8 + 2 * tq);
        s[nf][0] = __expf(s[nf][0] * scale + b0.x);
        s[nf][1] = __expf(s[nf][1] * scale + b0.y);
        s[nf][2] = __expf(s[nf][2] * scale + b1.x);
        s[nf][3] = __expf(s[nf][3] * scale + b1.y);
        slo += s[nf][0] + s[nf][1];
        shi += s[nf][2] + s[nf][3];
    }
    slo += __shfl_xor_sync(0xffffffffu, slo, 1);
    slo += __shfl_xor_sync(0xffffffffu, slo, 2);
    shi += __shfl_xor_sync(0xffffffffu, shi, 1);
    shi += __shfl_xor_sync(0xffffffffu, shi, 2);
    float il = 1.0f / slo, ih = 1.0f / shi;

    // O = P V : P accumulators repack into A-fragments
    float o[4][4] = {};
    uint32_t vbase = smem_u32(&Vs[0][0]) + (uint32_t)(lane & 15) * RPB;
#pragma unroll
    for (int kf = 0; kf < 4; kf++) {
        uint4 ap;
        ap.x = pk(s[2 * kf][0], s[2 * kf][1]);
        ap.y = pk(s[2 * kf][2], s[2 * kf][3]);
        ap.z = pk(s[2 * kf + 1][0], s[2 * kf + 1][1]);
        ap.w = pk(s[2 * kf + 1][2], s[2 * kf + 1][3]);
        uint32_t rowaddr = vbase + (uint32_t)kf * 16 * RPB;
#pragma unroll
        for (int nf = 0; nf < 4; nf++) {
            uint2 bv = ldsm_x2_trans(rowaddr + nf * 16);
            mma16(o[nf], ap, bv);
        }
    }

    bf16* ob = out + ((size_t)b * 64 + w * 16) * 256 + h * 32;
#pragma unroll
    for (int nf = 0; nf < 4; nf++) {
        int col = nf * 8 + 2 * tq;
        *(uint32_t*)(ob + (size_t)g * 256 + col) = pk(o[nf][0] * il, o[nf][1] * il);
        *(uint32_t*)(ob + (size_t)(g + 8) * 256 + col) = pk(o[nf][2] * ih, o[nf][3] * ih);
    }
}

// ---------------------------------------------------------------------------
// launch
// ---------------------------------------------------------------------------
extern "C" void kernel_launch(void* const* d_in, const int* in_sizes, int n_in,
                              void* d_out, int out_size) {
    const float* x     = (const float*)d_in[0];
    const float* y     = (const float*)d_in[1];
    const float* Wqkv1 = (const float*)d_in[2];
    const float* bqkv1 = (const float*)d_in[3];
    const float* Wqkv2 = (const float*)d_in[4];
    const float* bqkv2 = (const float*)d_in[5];
    const float* bias1 = (const float*)d_in[6];
    const float* bias2 = (const float*)d_in[7];
    const float* Wp1   = (const float*)d_in[8];
    const float* bp1   = (const float*)d_in[9];
    const float* Wp2   = (const float*)d_in[10];
    const float* bp2   = (const float*)d_in[11];
    const float* g1    = (const float*)d_in[12];
    const float* be1   = (const float*)d_in[13];
    const float* g2    = (const float*)d_in[14];
    const float* be2   = (const float*)d_in[15];
    float* out = (float*)d_out;

    bf16 *qkv1, *qkv2, *o1, *o2, *wtq1, *wtq2, *wtp1, *wtp2;
    cudaGetSymbolAddress((void**)&qkv1, g_qkv1);
    cudaGetSymbolAddress((void**)&qkv2, g_qkv2);
    cudaGetSymbolAddress((void**)&o1, g_o1);
    cudaGetSymbolAddress((void**)&o2, g_o2);
    cudaGetSymbolAddress((void**)&wtq1, g_wtq1);
    cudaGetSymbolAddress((void**)&wtq2, g_wtq2);
    cudaGetSymbolAddress((void**)&wtp1, g_wtp1);
    cudaGetSymbolAddress((void**)&wtp2, g_wtp2);

    // phase 0: all weight transposes in one launch
    transpose_all<<<dim3(24, 8, 4), dim3(32, 8)>>>(Wqkv1, wtq1, Wqkv2, wtq2,
                                                   Wp1, wtp1, Wp2, wtp2);

    // phase 1: QKV projections, both directions
    gemm_qkv<<<dim3(6, Mrows / 128, 2), 256>>>(x, y, wtq1, wtq2, bqkv1, bqkv2,
                                               qkv1, qkv2);

    // phase 2: cross attention, both directions
    attn_tc<<<dim3(Bwin, Hh, 2), 128>>>(qkv1, qkv2, bias1, bias2, o1, o2);

    // phase 3+4: fused proj + residual + LayerNorm, both directions
    proj_ln<<<dim3(Mrows / 64, 1, 2), 256>>>(o1, o2, wtp1, wtp2, bp1, bp2,
                                             x, y, g1, be1, g2, be2, out);
}

// round 7
// speedup vs baseline: 5.5685x; 1.0650x over previous
#include <cuda_runtime.h>
#include <cuda_bf16.h>
#include <math.h>
#include <stdint.h>

// ---------------------------------------------------------------------------
// WindowCrossAttention  B=4096, N=64, C=256, H=8, Dh=32
// Round 7: cp.async 3-stage pipelines (1 barrier/chunk), XOR-swizzled 64B-row
// smem tiles (conflict-free ldmatrix, smaller footprint), proj_ln at 3 CTAs/SM.
// ---------------------------------------------------------------------------

#define Bwin 4096
#define Hh   8
#define Mrows (Bwin * 64)              // 262144

typedef __nv_bfloat16 bf16;

// scratch (static device arrays; no allocations allowed)
__device__ bf16  g_qkv1[(size_t)Mrows * 768];
__device__ bf16  g_qkv2[(size_t)Mrows * 768];
__device__ bf16  g_o1[(size_t)Mrows * 256];
__device__ bf16  g_o2[(size_t)Mrows * 256];
__device__ bf16  g_wtq1[768 * 256];
__device__ bf16  g_wtq2[768 * 256];
__device__ bf16  g_wtp1[256 * 256];
__device__ bf16  g_wtp2[256 * 256];

__device__ __forceinline__ uint32_t pk(float lo, float hi) {
    __nv_bfloat162 t = __float22bfloat162_rn(make_float2(lo, hi));
    return *reinterpret_cast<uint32_t*>(&t);
}
__device__ __forceinline__ uint32_t smem_u32(const void* p) {
    uint32_t a;
    asm("{ .reg .u64 t; cvta.to.shared.u64 t, %1; cvt.u32.u64 %0, t; }"
        : "=r"(a) : "l"(p));
    return a;
}
__device__ __forceinline__ void mma16(float* c, uint4 a, uint2 b) {
    asm volatile(
        "mma.sync.aligned.m16n8k16.row.col.f32.bf16.bf16.f32 "
        "{%0,%1,%2,%3}, {%4,%5,%6,%7}, {%8,%9}, {%0,%1,%2,%3};"
        : "+f"(c[0]), "+f"(c[1]), "+f"(c[2]), "+f"(c[3])
        : "r"(a.x), "r"(a.y), "r"(a.z), "r"(a.w), "r"(b.x), "r"(b.y));
}
__device__ __forceinline__ uint4 ldsm_x4(uint32_t addr) {
    uint4 r;
    asm volatile("ldmatrix.sync.aligned.m8n8.x4.shared.b16 {%0,%1,%2,%3}, [%4];"
                 : "=r"(r.x), "=r"(r.y), "=r"(r.z), "=r"(r.w) : "r"(addr));
    return r;
}
__device__ __forceinline__ uint2 ldsm_x2_trans(uint32_t addr) {
    uint2 r;
    asm volatile("ldmatrix.sync.aligned.m8n8.x2.trans.shared.b16 {%0,%1}, [%2];"
                 : "=r"(r.x), "=r"(r.y) : "r"(addr));
    return r;
}
__device__ __forceinline__ void cp16(uint32_t dst, const void* src) {
    asm volatile("cp.async.cg.shared.global [%0], [%1], 16;"
                 :: "r"(dst), "l"(src));
}
__device__ __forceinline__ void cp_commit() {
    asm volatile("cp.async.commit_group;" ::: "memory");
}
template <int N>
__device__ __forceinline__ void cp_wait() {
    asm volatile("cp.async.wait_group %0;" :: "n"(N) : "memory");
}

// XOR swizzle: 64B rows (4 x 16B granules), phys granule = g ^ ((row>>1)&3)
#define SWZ(row, g) ((uint32_t)((row) * 64 + (((g) ^ (((row) >> 1) & 3)) * 16)))

// attention smem padding (unchanged from R6)
#define RP 40
#define RPB 80

// ---------------------------------------------------------------------------
// Weight transposes (all four in one launch, z selects)
// ---------------------------------------------------------------------------
__global__ void transpose_all(const float* __restrict__ Wq1, bf16* __restrict__ Tq1,
                              const float* __restrict__ Wq2, bf16* __restrict__ Tq2,
                              const float* __restrict__ Wp1, bf16* __restrict__ Tp1,
                              const float* __restrict__ Wp2, bf16* __restrict__ Tp2) {
    const float* W;
    bf16* Wt;
    int Nc;
    switch (blockIdx.z) {
        case 0: W = Wq1; Wt = Tq1; Nc = 768; break;
        case 1: W = Wq2; Wt = Tq2; Nc = 768; break;
        case 2: W = Wp1; Wt = Tp1; Nc = 256; break;
        default: W = Wp2; Wt = Tp2; Nc = 256; break;
    }
    if (blockIdx.x * 32 >= Nc) return;
    __shared__ float tile[32][33];
    int n0 = blockIdx.x * 32;
    int k0 = blockIdx.y * 32;
    int tx = threadIdx.x, ty = threadIdx.y;
#pragma unroll
    for (int r = 0; r < 4; r++)
        tile[ty + 8 * r][tx] = W[(size_t)(k0 + ty + 8 * r) * Nc + n0 + tx];
    __syncthreads();
#pragma unroll
    for (int r = 0; r < 4; r++)
        Wt[(size_t)(n0 + ty + 8 * r) * 256 + k0 + tx] =
            __float2bfloat16_rn(tile[tx][ty + 8 * r]);
}

// ---------------------------------------------------------------------------
// QKV GEMM: CTA 128x128, 8 warps (2m x 4n), BK=32. A fp32 reg-staged (cvt on
// STS), B via cp.async. 3-stage smem, 1 barrier/chunk. grid.z = direction.
// ---------------------------------------------------------------------------
__global__ __launch_bounds__(256, 2)
void gemm_qkv(const float* __restrict__ x, const float* __restrict__ y,
              const bf16* __restrict__ wt1, const bf16* __restrict__ wt2,
              const float* __restrict__ bq1, const float* __restrict__ bq2,
              bf16* __restrict__ c1, bf16* __restrict__ c2) {
    __shared__ __align__(16) bf16 As[3][128][32];   // 24KB
    __shared__ __align__(16) bf16 Bs[3][128][32];   // 24KB
    const int Nc = 768;
    const uint32_t ABYTES = 128 * 64, BBYTES = 128 * 64;

    const float* A    = blockIdx.z ? y : x;
    const bf16* Bt    = blockIdx.z ? wt2 : wt1;
    const float* bias = blockIdx.z ? bq2 : bq1;
    bf16* C           = blockIdx.z ? c2 : c1;

    const int t = threadIdx.x;
    const int w = t >> 5, lane = t & 31;
    const int warp_m = w >> 2, warp_n = w & 3;
    const int mBase = blockIdx.y * 128, nBase = blockIdx.x * 128;

    const float* Ab = A + (size_t)mBase * 256;
    const bf16*  Bb = Bt + (size_t)nBase * 256;

    const int lr = t >> 2;          // 0..63
    const int lg = t & 3;           // granule
    const uint32_t swA0 = SWZ(lr, lg);            // rows lr / lr+64: same sel
    const uint32_t swA1 = SWZ(lr + 64, lg);
    const uint32_t aSm = smem_u32(&As[0][0][0]);
    const uint32_t bSm = smem_u32(&Bs[0][0][0]);

    float4 s0[2], s1[2];
    auto LDGA = [&](int kc) {
#pragma unroll
        for (int rr = 0; rr < 2; rr++) {
            const float* p = Ab + (size_t)(lr + rr * 64) * 256 + kc + lg * 8;
            s0[rr] = *(const float4*)p;
            s1[rr] = *(const float4*)(p + 4);
        }
    };
    auto STSA = [&](int buf) {
        uint4 v0 = { pk(s0[0].x, s0[0].y), pk(s0[0].z, s0[0].w),
                     pk(s1[0].x, s1[0].y), pk(s1[0].z, s1[0].w) };
        uint4 v1 = { pk(s0[1].x, s0[1].y), pk(s0[1].z, s0[1].w),
                     pk(s1[1].x, s1[1].y), pk(s1[1].z, s1[1].w) };
        *(uint4*)((char*)&As[buf][0][0] + swA0) = v0;
        *(uint4*)((char*)&As[buf][0][0] + swA1) = v1;
    };
    auto CPB = [&](int kc, int buf) {
#pragma unroll
        for (int rr = 0; rr < 2; rr++) {
            int row = lr + rr * 64;
            cp16(bSm + (uint32_t)buf * BBYTES + SWZ(row, lg),
                 Bb + (size_t)row * 256 + kc + lg * 8);
        }
        cp_commit();
    };

    // ldmatrix lane addresses
    const int row0a = warp_m * 64 + (lane & 15);
    const int sela = (row0a >> 1) & 3;
    const int hia = lane >> 4;
    const uint32_t ga0 = (uint32_t)((hia ^ sela) * 16);
    const uint32_t ga1 = (uint32_t)(((2 + hia) ^ sela) * 16);
    const uint32_t aAddr = aSm + (uint32_t)row0a * 64;

    const int row0b = warp_n * 32 + (lane & 7) + ((lane >> 4) & 1) * 8;
    const int selb = (row0b >> 1) & 3;
    const int hib = (lane >> 3) & 1;
    const uint32_t gb0 = (uint32_t)((hib ^ selb) * 16);
    const uint32_t gb1 = (uint32_t)(((2 + hib) ^ selb) * 16);
    const uint32_t bAddr = bSm + (uint32_t)row0b * 64;

    float acc[4][4][4] = {};

    LDGA(0);
    STSA(0);
    CPB(0, 0);
    CPB(32, 1);
    LDGA(32);

    int b3 = 0, st3 = 1, cp3 = 2;
#pragma unroll 1
    for (int c = 0; c < 8; c++) {
        if (c < 7) cp_wait<1>(); else cp_wait<0>();
        __syncthreads();
        if (c < 7) STSA(st3);
        if (c < 6) CPB((c + 2) * 32, cp3);
        if (c < 6) LDGA((c + 2) * 32);

        const uint32_t ab = aAddr + (uint32_t)b3 * ABYTES;
        const uint32_t bb = bAddr + (uint32_t)b3 * BBYTES;
#pragma unroll
        for (int kf = 0; kf < 2; kf++) {
            const uint32_t go_a = kf ? ga1 : ga0;
            const uint32_t go_b = kf ? gb1 : gb0;
            uint4 av[4];
#pragma unroll
            for (int mf = 0; mf < 4; mf++)
                av[mf] = ldsm_x4(ab + (uint32_t)mf * 1024 + go_a);
            uint4 bp0 = ldsm_x4(bb + go_b);
            uint4 bp1 = ldsm_x4(bb + 1024 + go_b);
            uint2 bv[4] = { {bp0.x, bp0.y}, {bp0.z, bp0.w},
                            {bp1.x, bp1.y}, {bp1.z, bp1.w} };
#pragma unroll
            for (int mf = 0; mf < 4; mf++)
#pragma unroll
                for (int nf = 0; nf < 4; nf++)
                    mma16(acc[mf][nf], av[mf], bv[nf]);
        }
        b3 = (b3 == 2) ? 0 : b3 + 1;
        st3 = (st3 == 2) ? 0 : st3 + 1;
        cp3 = (cp3 == 2) ? 0 : cp3 + 1;
    }

    // epilogue: bias add + bf16 store
    const int g = lane >> 2;
    const int tq = lane & 3;
    float2 bz[4];
#pragma unroll
    for (int nf = 0; nf < 4; nf++)
        bz[nf] = *(const float2*)(bias + nBase + warp_n * 32 + nf * 8 + 2 * tq);

#pragma unroll
    for (int mf = 0; mf < 4; mf++) {
        int row0 = mBase + warp_m * 64 + mf * 16 + g;
#pragma unroll
        for (int nf = 0; nf < 4; nf++) {
            int col = nBase + warp_n * 32 + nf * 8 + 2 * tq;
            *(uint32_t*)(C + (size_t)row0 * Nc + col) =
                pk(acc[mf][nf][0] + bz[nf].x, acc[mf][nf][1] + bz[nf].y);
            *(uint32_t*)(C + (size_t)(row0 + 8) * Nc + col) =
                pk(acc[mf][nf][2] + bz[nf].x, acc[mf][nf][3] + bz[nf].y);
        }
    }
}

// ---------------------------------------------------------------------------
// FUSED proj + bias + residual + LayerNorm.  CTA 64 x 256, 8 warps n-split,
// BK=32, all-cp.async 3-stage, 1 barrier/chunk, 3 CTAs/SM.  grid.z = dir.
// ---------------------------------------------------------------------------
__global__ __launch_bounds__(256, 3)
void proj_ln(const bf16* __restrict__ o1, const bf16* __restrict__ o2,
             const bf16* __restrict__ wt1, const bf16* __restrict__ wt2,
             const float* __restrict__ bp1, const float* __restrict__ bp2,
             const float* __restrict__ x, const float* __restrict__ y,
             const float* __restrict__ g1, const float* __restrict__ be1,
             const float* __restrict__ g2, const float* __restrict__ be2,
             float* __restrict__ outbase) {
    __shared__ __align__(16) bf16 As[3][64][32];    // 12KB
    __shared__ __align__(16) bf16 Bs[3][256][32];   // 48KB
    __shared__ float2 red[64][8];
    __shared__ float2 mv[64];
    const uint32_t ABYTES = 64 * 64, BBYTES = 256 * 64;

    const bf16* A      = blockIdx.z ? o2 : o1;
    const bf16* Bt     = blockIdx.z ? wt2 : wt1;
    const float* bias  = blockIdx.z ? bp2 : bp1;
    const float* resid = blockIdx.z ? y : x;
    const float* gamma = blockIdx.z ? g2 : g1;
    const float* beta  = blockIdx.z ? be2 : be1;
    float* out = outbase + (size_t)blockIdx.z * Mrows * 256;

    const int t = threadIdx.x;
    const int w = t >> 5, lane = t & 31;
    const int g = lane >> 2, tq = lane & 3;
    const int mBase = blockIdx.x * 64;

    const bf16* Ab = A + (size_t)mBase * 256;

    const int lr = t >> 2, lg = t & 3;
    const uint32_t aSm = smem_u32(&As[0][0][0]);
    const uint32_t bSm = smem_u32(&Bs[0][0][0]);

    auto CPAB = [&](int kc, int buf) {
        cp16(aSm + (uint32_t)buf * ABYTES + SWZ(lr, lg),
             Ab + (size_t)lr * 256 + kc + lg * 8);
#pragma unroll
        for (int rr = 0; rr < 4; rr++) {
            int row = lr + rr * 64;
            cp16(bSm + (uint32_t)buf * BBYTES + SWZ(row, lg),
                 Bt + (size_t)row * 256 + kc + lg * 8);
        }
        cp_commit();
    };

    const int row0a = lane & 15;
    const int sela = (row0a >> 1) & 3;
    const int hia = lane >> 4;
    const uint32_t ga0 = (uint32_t)((hia ^ sela) * 16);
    const uint32_t ga1 = (uint32_t)(((2 + hia) ^ sela) * 16);
    const uint32_t aAddr = aSm + (uint32_t)row0a * 64;

    const int row0b = w * 32 + (lane & 7) + ((lane >> 4) & 1) * 8;
    const int selb = (row0b >> 1) & 3;
    const int hib = (lane >> 3) & 1;
    const uint32_t gb0 = (uint32_t)((hib ^ selb) * 16);
    const uint32_t gb1 = (uint32_t)(((2 + hib) ^ selb) * 16);
    const uint32_t bAddr = bSm + (uint32_t)row0b * 64;

    float acc[4][4][4] = {};

    CPAB(0, 0);
    CPAB(32, 1);

    int b3 = 0, cp3 = 2;
#pragma unroll 1
    for (int c = 0; c < 8; c++) {
        if (c < 7) cp_wait<1>(); else cp_wait<0>();
        __syncthreads();
        if (c < 6) CPAB((c + 2) * 32, cp3);

        const uint32_t ab = aAddr + (uint32_t)b3 * ABYTES;
        const uint32_t bb = bAddr + (uint32_t)b3 * BBYTES;
#pragma unroll
        for (int kf = 0; kf < 2; kf++) {
            const uint32_t go_a = kf ? ga1 : ga0;
            const uint32_t go_b = kf ? gb1 : gb0;
            uint4 av[4];
#pragma unroll
            for (int mf = 0; mf < 4; mf++)
                av[mf] = ldsm_x4(ab + (uint32_t)mf * 1024 + go_a);
            uint4 bp0 = ldsm_x4(bb + go_b);
            uint4 bp1 = ldsm_x4(bb + 1024 + go_b);
            uint2 bv[4] = { {bp0.x, bp0.y}, {bp0.z, bp0.w},
                            {bp1.x, bp1.y}, {bp1.z, bp1.w} };
#pragma unroll
            for (int mf = 0; mf < 4; mf++)
#pragma unroll
                for (int nf = 0; nf < 4; nf++)
                    mma16(acc[mf][nf], av[mf], bv[nf]);
        }
        b3 = (b3 == 2) ? 0 : b3 + 1;
        cp3 = (cp3 == 2) ? 0 : cp3 + 1;
    }

    // epilogue pass 1: val = acc + bias + resid, per-row partial stats
    float2 bz[4];
#pragma unroll
    for (int nf = 0; nf < 4; nf++)
        bz[nf] = *(const float2*)(bias + w * 32 + nf * 8 + 2 * tq);

#pragma unroll
    for (int mf = 0; mf < 4; mf++) {
        int r0 = mf * 16 + g;
        float plo = 0.0f, phi = 0.0f, qlo = 0.0f, qhi = 0.0f;
#pragma unroll
        for (int nf = 0; nf < 4; nf++) {
            int col = w * 32 + nf * 8 + 2 * tq;
            float2 x0 = *(const float2*)(resid + (size_t)(mBase + r0) * 256 + col);
            float2 x1 = *(const float2*)(resid + (size_t)(mBase + r0 + 8) * 256 + col);
            float v0 = acc[mf][nf][0] + bz[nf].x + x0.x;
            float v1 = acc[mf][nf][1] + bz[nf].y + x0.y;
            float v2 = acc[mf][nf][2] + bz[nf].x + x1.x;
            float v3 = acc[mf][nf][3] + bz[nf].y + x1.y;
            acc[mf][nf][0] = v0; acc[mf][nf][1] = v1;
            acc[mf][nf][2] = v2; acc[mf][nf][3] = v3;
            plo += v0 + v1; phi += v2 + v3;
            qlo += v0 * v0 + v1 * v1; qhi += v2 * v2 + v3 * v3;
        }
        plo += __shfl_xor_sync(0xffffffffu, plo, 1);
        plo += __shfl_xor_sync(0xffffffffu, plo, 2);
        qlo += __shfl_xor_sync(0xffffffffu, qlo, 1);
        qlo += __shfl_xor_sync(0xffffffffu, qlo, 2);
        phi += __shfl_xor_sync(0xffffffffu, phi, 1);
        phi += __shfl_xor_sync(0xffffffffu, phi, 2);
        qhi += __shfl_xor_sync(0xffffffffu, qhi, 1);
        qhi += __shfl_xor_sync(0xffffffffu, qhi, 2);
        if (tq == 0) {
            red[r0][w]     = make_float2(plo, qlo);
            red[r0 + 8][w] = make_float2(phi, qhi);
        }
    }
    __syncthreads();

    if (t < 64) {
        float s = 0.0f, q = 0.0f;
#pragma unroll
        for (int j = 0; j < 8; j++) { s += red[t][j].x; q += red[t][j].y; }
        float mean = s * (1.0f / 256.0f);
        float var = q * (1.0f / 256.0f) - mean * mean;
        mv[t] = make_float2(mean, rsqrtf(var + 1e-5f));
    }
    __syncthreads();

    // epilogue pass 2: normalize + affine + store
#pragma unroll
    for (int nf = 0; nf < 4; nf++) {
        int col = w * 32 + nf * 8 + 2 * tq;
        float2 gm = *(const float2*)(gamma + col);
        float2 bt = *(const float2*)(beta + col);
#pragma unroll
        for (int mf = 0; mf < 4; mf++) {
            int r0 = mf * 16 + g;
            float2 m0 = mv[r0];
            float2 m1 = mv[r0 + 8];
            float2 u0 = { (acc[mf][nf][0] - m0.x) * m0.y * gm.x + bt.x,
                          (acc[mf][nf][1] - m0.x) * m0.y * gm.y + bt.y };
            float2 u1 = { (acc[mf][nf][2] - m1.x) * m1.y * gm.x + bt.x,
                          (acc[mf][nf][3] - m1.x) * m1.y * gm.y + bt.y };
            *(float2*)(out + (size_t)(mBase + r0) * 256 + col) = u0;
            *(float2*)(out + (size_t)(mBase + r0 + 8) * 256 + col) = u1;
        }
    }
}

// ---------------------------------------------------------------------------
// Tensor-core attention: block per (b,h), 128 threads (4 warps), grid.z = dir.
// ---------------------------------------------------------------------------
__global__ __launch_bounds__(128)
void attn_tc(const bf16* __restrict__ qkv1, const bf16* __restrict__ qkv2,
             const float* __restrict__ bias1, const float* __restrict__ bias2,
             bf16* __restrict__ o1, bf16* __restrict__ o2) {
    const bf16* qkvQ  = blockIdx.z ? qkv2 : qkv1;
    const bf16* qkvKV = blockIdx.z ? qkv1 : qkv2;
    const float* bias = blockIdx.z ? bias2 : bias1;
    bf16* out         = blockIdx.z ? o2 : o1;

    const int b = blockIdx.x;
    const int h = blockIdx.y;
    const int t = threadIdx.x;
    const int w = t >> 5;
    const int lane = t & 31;
    const int g = lane >> 2;
    const int tq = lane & 3;

    __shared__ __align__(16) bf16 Ks[64][RP];
    __shared__ __align__(16) bf16 Vs[64][RP];

    const bf16* base = qkvKV + (size_t)b * 64 * 768;
    {
        const int lr = t >> 2, lg = t & 3;
#pragma unroll
        for (int rr = 0; rr < 2; rr++) {
            int row = lr + rr * 32;
            const bf16* src = base + (size_t)row * 768 + h * 32 + lg * 8;
            *(uint4*)&Ks[row][lg * 8] = *(const uint4*)(src + 256);
            *(uint4*)&Vs[row][lg * 8] = *(const uint4*)(src + 512);
        }
    }
    __syncthreads();

    const bf16* Qb = qkvQ + ((size_t)b * 64 + w * 16) * 768 + h * 32;
    uint4 aq[2];
#pragma unroll
    for (int kf = 0; kf < 2; kf++) {
        const bf16* p = Qb + kf * 16;
        aq[kf].x = *(const uint32_t*)(p + (size_t)g * 768 + 2 * tq);
        aq[kf].y = *(const uint32_t*)(p + (size_t)(g + 8) * 768 + 2 * tq);
        aq[kf].z = *(const uint32_t*)(p + (size_t)g * 768 + 2 * tq + 8);
        aq[kf].w = *(const uint32_t*)(p + (size_t)(g + 8) * 768 + 2 * tq + 8);
    }

    uint32_t k_base = smem_u32(&Ks[0][0]) +
        (uint32_t)((lane & 7) + ((lane >> 4) & 1) * 8) * RPB +
        (uint32_t)((lane >> 3) & 1) * 16;
    float s[8][4] = {};
#pragma unroll
    for (int p = 0; p < 4; p++) {
        uint32_t pa = k_base + (uint32_t)p * 16 * RPB;
#pragma unroll
        for (int kf = 0; kf < 2; kf++) {
            uint4 bp = ldsm_x4(pa + (uint32_t)kf * 32);
            mma16(s[2 * p],     aq[kf], make_uint2(bp.x, bp.y));
            mma16(s[2 * p + 1], aq[kf], make_uint2(bp.z, bp.w));
        }
    }

    const float* bb = bias + (size_t)h * 4096 + (size_t)(w * 16 + g) * 64;
    const float scale = 0.0625f;
    float slo = 0.0f, shi = 0.0f;
#pragma unroll
    for (int nf = 0; nf < 8; nf++) {
        float2 b0 = *(const float2*)(bb + nf * 8 + 2 * tq);
        float2 b1 = *(const float2*)(bb + 8 * 64 + nf * 8 + 2 * tq);
        s[nf][0] = __expf(s[nf][0] * scale + b0.x);
        s[nf][1] = __expf(s[nf][1] * scale + b0.y);
        s[nf][2] = __expf(s[nf][2] * scale + b1.x);
        s[nf][3] = __expf(s[nf][3] * scale + b1.y);
        slo += s[nf][0] + s[nf][1];
        shi += s[nf][2] + s[nf][3];
    }
    slo += __shfl_xor_sync(0xffffffffu, slo, 1);
    slo += __shfl_xor_sync(0xffffffffu, slo, 2);
    shi += __shfl_xor_sync(0xffffffffu, shi, 1);
    shi += __shfl_xor_sync(0xffffffffu, shi, 2);
    float il = 1.0f / slo, ih = 1.0f / shi;

    float o[4][4] = {};
    uint32_t vbase = smem_u32(&Vs[0][0]) + (uint32_t)(lane & 15) * RPB;
#pragma unroll
    for (int kf = 0; kf < 4; kf++) {
        uint4 ap;
        ap.x = pk(s[2 * kf][0], s[2 * kf][1]);
        ap.y = pk(s[2 * kf][2], s[2 * kf][3]);
        ap.z = pk(s[2 * kf + 1][0], s[2 * kf + 1][1]);
        ap.w = pk(s[2 * kf + 1][2], s[2 * kf + 1][3]);
        uint32_t rowaddr = vbase + (uint32_t)kf * 16 * RPB;
#pragma unroll
        for (int nf = 0; nf < 4; nf++) {
            uint2 bv = ldsm_x2_trans(rowaddr + nf * 16);
            mma16(o[nf], ap, bv);
        }
    }

    bf16* ob = out + ((size_t)b * 64 + w * 16) * 256 + h * 32;
#pragma unroll
    for (int nf = 0; nf < 4; nf++) {
        int col = nf * 8 + 2 * tq;
        *(uint32_t*)(ob + (size_t)g * 256 + col) = pk(o[nf][0] * il, o[nf][1] * il);
        *(uint32_t*)(ob + (size_t)(g + 8) * 256 + col) = pk(o[nf][2] * ih, o[nf][3] * ih);
    }
}

// ---------------------------------------------------------------------------
// launch
// ---------------------------------------------------------------------------
extern "C" void kernel_launch(void* const* d_in, const int* in_sizes, int n_in,
                              void* d_out, int out_size) {
    const float* x     = (const float*)d_in[0];
    const float* y     = (const float*)d_in[1];
    const float* Wqkv1 = (const float*)d_in[2];
    const float* bqkv1 = (const float*)d_in[3];
    const float* Wqkv2 = (const float*)d_in[4];
    const float* bqkv2 = (const float*)d_in[5];
    const float* bias1 = (const float*)d_in[6];
    const float* bias2 = (const float*)d_in[7];
    const float* Wp1   = (const float*)d_in[8];
    const float* bp1   = (const float*)d_in[9];
    const float* Wp2   = (const float*)d_in[10];
    const float* bp2   = (const float*)d_in[11];
    const float* g1    = (const float*)d_in[12];
    const float* be1   = (const float*)d_in[13];
    const float* g2    = (const float*)d_in[14];
    const float* be2   = (const float*)d_in[15];
    float* out = (float*)d_out;

    bf16 *qkv1, *qkv2, *o1, *o2, *wtq1, *wtq2, *wtp1, *wtp2;
    cudaGetSymbolAddress((void**)&qkv1, g_qkv1);
    cudaGetSymbolAddress((void**)&qkv2, g_qkv2);
    cudaGetSymbolAddress((void**)&o1, g_o1);
    cudaGetSymbolAddress((void**)&o2, g_o2);
    cudaGetSymbolAddress((void**)&wtq1, g_wtq1);
    cudaGetSymbolAddress((void**)&wtq2, g_wtq2);
    cudaGetSymbolAddress((void**)&wtp1, g_wtp1);
    cudaGetSymbolAddress((void**)&wtp2, g_wtp2);

    transpose_all<<<dim3(24, 8, 4), dim3(32, 8)>>>(Wqkv1, wtq1, Wqkv2, wtq2,
                                                   Wp1, wtp1, Wp2, wtp2);

    gemm_qkv<<<dim3(6, Mrows / 128, 2), 256>>>(x, y, wtq1, wtq2, bqkv1, bqkv2,
                                               qkv1, qkv2);

    attn_tc<<<dim3(Bwin, Hh, 2), 128>>>(qkv1, qkv2, bias1, bias2, o1, o2);

    proj_ln<<<dim3(Mrows / 64, 1, 2), 256>>>(o1, o2, wtp1, wtp2, bp1, bp2,
                                             x, y, g1, be1, g2, be2, out);
}